// round 13
// baseline (speedup 1.0000x reference)
#include <cuda_runtime.h>
#include <cuda_fp16.h>
#include <math.h>
#include <stdint.h>

// ---------------- problem constants ----------------
#define Bn 2
#define Tn 2048
#define NH 16
#define NKV 4
#define HD 128
#define DMODEL 2048
#define KVDIM 512
#define QKVSTR 3072         // combined QKV row: Q[0:2048) K[2048:2560) V[2560:3072)
#define ROWS 4096           // Bn*Tn
#define GK 2048             // K dim of every GEMM

// ---------------- scratch (__device__ globals) ----------------
__device__ __half g_xh  [(size_t)ROWS * DMODEL];  // fp16 x
__device__ __half g_QKVh[(size_t)ROWS * QKVSTR];  // fp16 Q,K (roped in place); V region unused
__device__ __half g_Vh  [(size_t)ROWS * KVDIM];   // V fp16: [b][kvh][t][d]
__device__ __half g_Oh  [(size_t)ROWS * DMODEL];  // flash output fp16
__device__ __half g_wTh [(size_t)QKVSTR * GK];    // fused [wq;wk;wv] [N,K] K-major fp16
__device__ __half g_woTh[(size_t)DMODEL * GK];
__device__ float  g_invf[64];

// ---------------- PTX helpers (baseline sm_80+ only) ----------------
__device__ __forceinline__ uint32_t smem_u32(const void* p) {
    uint32_t a;
    asm("{ .reg .u64 t; cvta.to.shared.u64 t, %1; cvt.u32.u64 %0, t; }" : "=r"(a) : "l"(p));
    return a;
}
__device__ __forceinline__ uint32_t packh2(float lo, float hi) {   // {lo,hi} fp16x2
    uint32_t r; asm("cvt.rn.f16x2.f32 %0, %1, %2;" : "=r"(r) : "f"(hi), "f"(lo)); return r;
}
__device__ __forceinline__ uint32_t ex2h2(uint32_t x) {            // 2^x on both halves
    uint32_t r; asm("ex2.approx.f16x2 %0, %1;" : "=r"(r) : "r"(x)); return r;
}
__device__ __forceinline__ uint32_t swz(uint32_t off) {   // SW128: bits[6:4] ^= bits[9:7]
    return off ^ ((off >> 3) & 0x70);
}
__device__ __forceinline__ void cp16(uint32_t dst, const void* src) {
    asm volatile("cp.async.cg.shared.global [%0], [%1], 16;" :: "r"(dst), "l"(src) : "memory");
}
#define CP_COMMIT() asm volatile("cp.async.commit_group;" ::: "memory")
#define CP_WAIT(n)  asm volatile("cp.async.wait_group %0;" :: "n"(n) : "memory")

__device__ __forceinline__ void ldsm_x4(uint32_t* r, uint32_t addr) {
    asm volatile("ldmatrix.sync.aligned.m8n8.x4.shared.b16 {%0,%1,%2,%3}, [%4];"
                 : "=r"(r[0]), "=r"(r[1]), "=r"(r[2]), "=r"(r[3]) : "r"(addr));
}
__device__ __forceinline__ void ldsm_x4_trans(uint32_t* r, uint32_t addr) {
    asm volatile("ldmatrix.sync.aligned.m8n8.x4.trans.shared.b16 {%0,%1,%2,%3}, [%4];"
                 : "=r"(r[0]), "=r"(r[1]), "=r"(r[2]), "=r"(r[3]) : "r"(addr));
}
__device__ __forceinline__ void mma_f16(float* d, const uint32_t* a, const uint32_t* b) {
    asm volatile(
        "mma.sync.aligned.m16n8k16.row.col.f32.f16.f16.f32 "
        "{%0,%1,%2,%3}, {%4,%5,%6,%7}, {%8,%9}, {%0,%1,%2,%3};"
        : "+f"(d[0]), "+f"(d[1]), "+f"(d[2]), "+f"(d[3])
        : "r"(a[0]), "r"(a[1]), "r"(a[2]), "r"(a[3]), "r"(b[0]), "r"(b[1]));
}

// ---------------- fused prep kernel ----------------
#define TR_BLOCKS 10240
#define RND_BLOCKS 8192
#define PREP_BLOCKS (TR_BLOCKS + RND_BLOCKS + 1)

__global__ void prep_kernel(const float* __restrict__ x,
                            const float* __restrict__ wq, const float* __restrict__ wk,
                            const float* __restrict__ wv, const float* __restrict__ wo,
                            __half* __restrict__ xh, __half* __restrict__ wTh,
                            __half* __restrict__ woTh) {
    __shared__ float t[32][33];
    int blk = blockIdx.x;
    int tid = threadIdx.x;
    if (blk < TR_BLOCKS) {
        int tx = tid & 31, ty = tid >> 5;
        int bx = blk % 160, kb = blk / 160;
        const float* src; __half* dst; int N;
        if (bx < 64)       { src = wq; dst = wTh;                     N = 2048; }
        else if (bx < 80)  { src = wk; dst = wTh + (size_t)2048 * GK; N = 512;  bx -= 64; }
        else if (bx < 96)  { src = wv; dst = wTh + (size_t)2560 * GK; N = 512;  bx -= 80; }
        else               { src = wo; dst = woTh;                    N = 2048; bx -= 96; }
        int n0 = bx * 32, k0 = kb * 32;
#pragma unroll
        for (int i = ty; i < 32; i += 8)
            t[i][tx] = src[(size_t)(k0 + i) * N + n0 + tx];
        __syncthreads();
#pragma unroll
        for (int i = ty; i < 32; i += 8)
            dst[(size_t)(n0 + i) * GK + k0 + tx] = __float2half_rn(t[tx][i]);
    } else if (blk < TR_BLOCKS + RND_BLOCKS) {
        int i = (blk - TR_BLOCKS) * 256 + tid;
        float4 v = ((const float4*)x)[i];
        uint2 u;
        u.x = packh2(v.x, v.y);
        u.y = packh2(v.z, v.w);
        ((uint2*)xh)[i] = u;
    } else {
        if (tid < 64) g_invf[tid] = (float)exp(-((double)tid / 64.0) * log(10000.0));
    }
}

// ---------------- rope (in-place on fp16 QKVh, Q and K regions) -----------
#define ROPE_TOTQ (ROWS * NH * 64)
#define ROPE_TOTK (ROWS * NKV * 64)
#define ROPE_BLOCKS 20480

__global__ void rope_kernel(__half* __restrict__ QKVh) {
    int idx = blockIdx.x * 256 + threadIdx.x;
    int off; int nheads;
    if (idx < ROPE_TOTQ) { off = 0; nheads = NH; }
    else { idx -= ROPE_TOTQ; off = 2048; nheads = NKV; }
    int d    = idx & 63;
    int rest = idx >> 6;
    int hh   = rest % nheads;
    int row  = rest / nheads;
    int tt   = row & (Tn - 1);
    float ang = (float)tt * g_invf[d];
    float sn, cs;
    sincosf(ang, &sn, &cs);
    __half* p = QKVh + (size_t)row * QKVSTR + off + hh * HD + d;
    float x0 = __half2float(p[0]), x1 = __half2float(p[64]);
    p[0]  = __float2half_rn(x0 * cs - x1 * sn);
    p[64] = __float2half_rn(x1 * cs + x0 * sn);
}

// ---------------- fp16 mma.sync GEMM (occupancy 2, unchanged) --------------
#define BM 128
#define BN 128
#define NSTG 3
#define ASTG 16384
#define BSTG 16384
#define STG  (ASTG + BSTG)
#define GEMM_SMEM (NSTG * STG)   // 98304
#define KITERS 32

template <int MODE>
__global__ __launch_bounds__(256, 2)
void gemm_mma(const __half* __restrict__ A, const __half* __restrict__ Bt,
              void* __restrict__ Cout, int N) {
    extern __shared__ char dsm[];
    const uint32_t base = smem_u32(dsm);

    const int tid  = threadIdx.x;
    const int wid  = tid >> 5;
    const int lane = tid & 31;
    const int mb   = blockIdx.y * BM;
    const int nb   = blockIdx.x * BN;
    const int wm   = (wid & 1) * 64;
    const int wn   = (wid >> 1) * 32;

    const __half* Ag = A  + (size_t)mb * GK;
    const __half* Bg = Bt + (size_t)nb * GK;

    float acc[4][4][4];
#pragma unroll
    for (int mt = 0; mt < 4; mt++)
#pragma unroll
        for (int nt = 0; nt < 4; nt++)
#pragma unroll
            for (int q = 0; q < 4; q++) acc[mt][nt][q] = 0.f;

    auto issue = [&](int buf, int s) {
        uint32_t sa = base + (uint32_t)buf * STG;
        uint32_t sb = sa + ASTG;
        int k0 = s * 64;
#pragma unroll
        for (int i = 0; i < 4; i++) {
            int cc  = tid + i * 256;
            int row = cc >> 3, ch = cc & 7;
            uint32_t off = swz((uint32_t)(row * 128 + ch * 16));
            cp16(sa + off, Ag + (size_t)row * GK + k0 + ch * 8);
            cp16(sb + off, Bg + (size_t)row * GK + k0 + ch * 8);
        }
        CP_COMMIT();
    };

    issue(0, 0); issue(1, 1);

    const int a_r  = (lane & 7) + ((lane >> 3) & 1) * 8;
    const int a_kc = (lane >> 4);
    const int b_r  = (lane & 7) + (lane >> 4) * 8;
    const int b_kc = ((lane >> 3) & 1);

    int st = 0, stp = 2;
    for (int s = 0; s < KITERS; s++) {
        if (s + 2 < KITERS) CP_WAIT(1); else CP_WAIT(0);
        __syncthreads();
        if (s + 2 < KITERS) issue(stp, s + 2);

        uint32_t sa = base + (uint32_t)st * STG + (uint32_t)(wm * 128);
        uint32_t sb = base + (uint32_t)st * STG + ASTG + (uint32_t)(wn * 128);

#pragma unroll
        for (int ks = 0; ks < 4; ks++) {
            uint32_t afr[4][4];
            uint32_t bfr[4][2];
#pragma unroll
            for (int mt = 0; mt < 4; mt++)
                ldsm_x4(afr[mt], sa + swz((uint32_t)((mt * 16 + a_r) * 128 + (2 * ks + a_kc) * 16)));
            {
                uint32_t tmp[4];
                ldsm_x4(tmp, sb + swz((uint32_t)((b_r) * 128 + (2 * ks + b_kc) * 16)));
                bfr[0][0] = tmp[0]; bfr[0][1] = tmp[1];
                bfr[1][0] = tmp[2]; bfr[1][1] = tmp[3];
                ldsm_x4(tmp, sb + swz((uint32_t)((16 + b_r) * 128 + (2 * ks + b_kc) * 16)));
                bfr[2][0] = tmp[0]; bfr[2][1] = tmp[1];
                bfr[3][0] = tmp[2]; bfr[3][1] = tmp[3];
            }
#pragma unroll
            for (int mt = 0; mt < 4; mt++)
#pragma unroll
                for (int nt = 0; nt < 4; nt++)
                    mma_f16(acc[mt][nt], afr[mt], bfr[nt]);
        }
        st  = (st  == NSTG - 1) ? 0 : st + 1;
        stp = (stp == NSTG - 1) ? 0 : stp + 1;
    }

    const int g = lane >> 2;
    const int cq = (lane & 3) * 2;
#pragma unroll
    for (int mt = 0; mt < 4; mt++) {
        int row0 = mb + wm + mt * 16 + g;
#pragma unroll
        for (int nt = 0; nt < 4; nt++) {
            int col = nb + wn + nt * 8 + cq;
            if (MODE == 0) {
                float* C = (float*)Cout;
                *(float2*)(C + (size_t)row0 * N + col)       = make_float2(acc[mt][nt][0], acc[mt][nt][1]);
                *(float2*)(C + (size_t)(row0 + 8) * N + col) = make_float2(acc[mt][nt][2], acc[mt][nt][3]);
            } else {
                uint32_t w0 = packh2(acc[mt][nt][0], acc[mt][nt][1]);
                uint32_t w1 = packh2(acc[mt][nt][2], acc[mt][nt][3]);
                if (col < 2560) {
                    __half* C = (__half*)Cout;
                    *(uint32_t*)(C + (size_t)row0 * QKVSTR + col)       = w0;
                    *(uint32_t*)(C + (size_t)(row0 + 8) * QKVSTR + col) = w1;
                } else {
                    int rel = col - 2560;
                    int kvh = rel >> 7, d = rel & 127;
                    int b0 = row0 >> 11, t0 = row0 & (Tn - 1);
                    int b1 = (row0 + 8) >> 11, t1 = (row0 + 8) & (Tn - 1);
                    *(uint32_t*)(g_Vh + (((size_t)(b0 * NKV + kvh) * Tn + t0) * HD + d)) = w0;
                    *(uint32_t*)(g_Vh + (((size_t)(b1 * NKV + kvh) * Tn + t1) * HD + d)) = w1;
                }
            }
        }
    }
}

// ---------------- flash attention: 32 q-rows/warp, B/V frags amortized ----
// FM=128, 128 threads (4 warps x 32 rows = 2 m16-blocks each), FN=64.
// Smem: Q 32KB @0 ([dc(2) stride 16384][qrow(128)][128B]);
//       per KV buffer: K 16KB ([dc(2) stride 8192][key(64)][128B])
//                    + V 16KB ([dchunk(2) stride 8192][key(64)][128B]); x2.
#define FM 128
#define FN 64
#define KVBUF 32768
#define FLASH_SMEM (32768 + 2 * KVBUF)   // 98304
#define FTHREADS 128

__global__ __launch_bounds__(FTHREADS, 2)
void flash_mma(const __half* __restrict__ QKVh, const __half* __restrict__ Vh,
               __half* __restrict__ Oh) {
    extern __shared__ float sm[];
    const uint32_t base = smem_u32(sm);
    const int tid = threadIdx.x, wid = tid >> 5, lane = tid & 31;
    const int qb = (Tn / FM - 1) - blockIdx.x;   // heavy blocks first
    const int h = blockIdx.y, b = blockIdx.z;
    const int kvh = h >> 2;
    const int nkt = 2 * qb + 2;

    const __half* Qg = QKVh + ((size_t)(b * Tn + qb * FM)) * QKVSTR + h * HD;
    const __half* Kg = QKVh + ((size_t)(b * Tn)) * QKVSTR + 2048 + kvh * HD;
    const __half* Vg = Vh + ((size_t)(b * NKV + kvh)) * Tn * HD;

    // ---- Q tile: 2048 16B chunks (128 rows x 16 chunks)
#pragma unroll
    for (int i = 0; i < 16; i++) {
        int f = tid + i * FTHREADS;
        int qr = f >> 4, ch = f & 15;
        cp16(base + (uint32_t)((ch >> 3) * 16384) + swz((uint32_t)(qr * 128 + (ch & 7) * 16)),
             Qg + (size_t)qr * QKVSTR + ch * 8);
    }

    auto kv_issue = [&](int kt) {
        uint32_t kb = base + 32768u + (uint32_t)(kt & 1) * KVBUF;
        uint32_t vb = kb + 16384u;
        const __half* Ksrc = Kg + (size_t)(kt * FN) * QKVSTR;
        const __half* Vsrc = Vg + (size_t)(kt * FN) * HD;
#pragma unroll
        for (int i = 0; i < 8; i++) {          // K: 1024 chunks
            int f = tid + i * FTHREADS;
            int kr = f >> 4, ch = f & 15;
            cp16(kb + (uint32_t)((ch >> 3) * 8192) + swz((uint32_t)(kr * 128 + (ch & 7) * 16)),
                 Ksrc + (size_t)kr * QKVSTR + ch * 8);
        }
#pragma unroll
        for (int i = 0; i < 8; i++) {          // V: 1024 chunks
            int f = tid + i * FTHREADS;
            int key = f >> 4, ch = f & 15;
            cp16(vb + (uint32_t)((ch >> 3) * 8192) + swz((uint32_t)(key * 128 + (ch & 7) * 16)),
                 Vsrc + key * HD + ch * 8);
        }
        CP_COMMIT();
    };

    const int a_r  = (lane & 7) + ((lane >> 3) & 1) * 8;
    const int a_kc = lane >> 4;
    const int b_r  = (lane & 7) + (lane >> 4) * 8;
    const int b_kc = (lane >> 3) & 1;
    const int g    = lane >> 2;
    const int cq2  = (lane & 3) * 2;
    const int vrow = lane & 7;
    const int vmi  = lane >> 3;
    const float scale2 = 0.08838834764831843f * 1.4426950408889634f;
    const uint32_t ONESx2 = 0x3C003C00u;
    const uint32_t bones[2] = {ONESx2, ONESx2};

    float o[2][16][4];
#pragma unroll
    for (int mb = 0; mb < 2; mb++)
#pragma unroll
        for (int nt = 0; nt < 16; nt++)
#pragma unroll
            for (int q = 0; q < 4; q++) o[mb][nt][q] = 0.f;
    float lacc[2][4] = {{0.f, 0.f, 0.f, 0.f}, {0.f, 0.f, 0.f, 0.f}};
    float m0[2] = {-1e30f, -1e30f}, m1[2] = {-1e30f, -1e30f};

    kv_issue(0);

    for (int kt = 0; kt < nkt; kt++) {
        __syncthreads();
        if (kt + 1 < nkt) { kv_issue(kt + 1); CP_WAIT(1); }
        else              { CP_WAIT(0); }
        __syncthreads();

        uint32_t kb = base + 32768u + (uint32_t)(kt & 1) * KVBUF;
        uint32_t vb = kb + 16384u;

        // ---- S = Q @ K^T: 2 m-blocks share each B fragment
        float sacc[2][8][4];
#pragma unroll
        for (int mb = 0; mb < 2; mb++)
#pragma unroll
            for (int nt = 0; nt < 8; nt++)
#pragma unroll
                for (int q = 0; q < 4; q++) sacc[mb][nt][q] = 0.f;

#pragma unroll
        for (int ks = 0; ks < 8; ks++) {
            uint32_t af[2][4];
#pragma unroll
            for (int mb = 0; mb < 2; mb++)
                ldsm_x4(af[mb], base + (uint32_t)((ks >> 2) * 16384)
                            + swz((uint32_t)((wid * 32 + mb * 16 + a_r) * 128
                                             + ((ks & 3) * 2 + a_kc) * 16)));
            uint32_t bf[8][2];
#pragma unroll
            for (int np = 0; np < 4; np++) {
                uint32_t tmp[4];
                ldsm_x4(tmp, kb + (uint32_t)((ks >> 2) * 8192)
                             + swz((uint32_t)((np * 16 + b_r) * 128 + ((ks & 3) * 2 + b_kc) * 16)));
                bf[np * 2][0] = tmp[0]; bf[np * 2][1] = tmp[1];
                bf[np * 2 + 1][0] = tmp[2]; bf[np * 2 + 1][1] = tmp[3];
            }
#pragma unroll
            for (int mb = 0; mb < 2; mb++)
#pragma unroll
                for (int nt = 0; nt < 8; nt++) mma_f16(sacc[mb][nt], af[mb], bf[nt]);
        }

        // ---- scale + causal mask; softmax per m-block
        uint32_t pf[2][4][4];
#pragma unroll
        for (int mb = 0; mb < 2; mb++) {
            int rl0 = wid * 32 + mb * 16 + g, rl1 = rl0 + 8;
            if (kt >= 2 * qb) {
                int kbl = (kt - 2 * qb) * 64;
#pragma unroll
                for (int nt = 0; nt < 8; nt++) {
                    int kc0 = kbl + nt * 8 + cq2;
                    sacc[mb][nt][0] = (kc0     > rl0) ? -1e30f : sacc[mb][nt][0] * scale2;
                    sacc[mb][nt][1] = (kc0 + 1 > rl0) ? -1e30f : sacc[mb][nt][1] * scale2;
                    sacc[mb][nt][2] = (kc0     > rl1) ? -1e30f : sacc[mb][nt][2] * scale2;
                    sacc[mb][nt][3] = (kc0 + 1 > rl1) ? -1e30f : sacc[mb][nt][3] * scale2;
                }
            } else {
#pragma unroll
                for (int nt = 0; nt < 8; nt++)
#pragma unroll
                    for (int q = 0; q < 4; q++) sacc[mb][nt][q] *= scale2;
            }

            float mx0 = -1e30f, mx1 = -1e30f;
#pragma unroll
            for (int nt = 0; nt < 8; nt++) {
                mx0 = fmaxf(mx0, fmaxf(sacc[mb][nt][0], sacc[mb][nt][1]));
                mx1 = fmaxf(mx1, fmaxf(sacc[mb][nt][2], sacc[mb][nt][3]));
            }
            mx0 = fmaxf(mx0, __shfl_xor_sync(0xffffffffu, mx0, 1));
            mx0 = fmaxf(mx0, __shfl_xor_sync(0xffffffffu, mx0, 2));
            mx1 = fmaxf(mx1, __shfl_xor_sync(0xffffffffu, mx1, 1));
            mx1 = fmaxf(mx1, __shfl_xor_sync(0xffffffffu, mx1, 2));
            float nm0 = fmaxf(m0[mb], mx0), nm1 = fmaxf(m1[mb], mx1);
            float al0 = exp2f(m0[mb] - nm0), al1 = exp2f(m1[mb] - nm1);
            m0[mb] = nm0; m1[mb] = nm1;

            // P = 2^(s-nm) in fp16x2; pf[mb][kc] IS the PV A-fragment
#pragma unroll
            for (int kc = 0; kc < 4; kc++) {
                pf[mb][kc][0] = ex2h2(packh2(sacc[mb][2 * kc][0] - nm0,     sacc[mb][2 * kc][1] - nm0));
                pf[mb][kc][1] = ex2h2(packh2(sacc[mb][2 * kc][2] - nm1,     sacc[mb][2 * kc][3] - nm1));
                pf[mb][kc][2] = ex2h2(packh2(sacc[mb][2 * kc + 1][0] - nm0, sacc[mb][2 * kc + 1][1] - nm0));
                pf[mb][kc][3] = ex2h2(packh2(sacc[mb][2 * kc + 1][2] - nm1, sacc[mb][2 * kc + 1][3] - nm1));
            }

            // rescale O + l
#pragma unroll
            for (int nt = 0; nt < 16; nt++) {
                o[mb][nt][0] *= al0; o[mb][nt][1] *= al0;
                o[mb][nt][2] *= al1; o[mb][nt][3] *= al1;
            }
            lacc[mb][0] *= al0; lacc[mb][1] *= al0;
            lacc[mb][2] *= al1; lacc[mb][3] *= al1;
#pragma unroll
            for (int kc = 0; kc < 4; kc++) mma_f16(lacc[mb], pf[mb][kc], bones);
        }

        // ---- O += P @ V : V fragments shared across both m-blocks
#pragma unroll
        for (int kc = 0; kc < 4; kc++) {
            int vkey = kc * 16 + (vmi & 1) * 8 + vrow;
#pragma unroll
            for (int np = 0; np < 16; np += 2) {
                int npp = np + (vmi >> 1);
                uint32_t tmp[4];
                ldsm_x4_trans(tmp, vb + (uint32_t)((npp >> 3) * 8192)
                                      + swz((uint32_t)(vkey * 128 + (npp & 7) * 16)));
#pragma unroll
                for (int mb = 0; mb < 2; mb++) {
                    mma_f16(o[mb][np],     pf[mb][kc], tmp);
                    mma_f16(o[mb][np + 1], pf[mb][kc], tmp + 2);
                }
            }
        }
    }

    // ---- epilogue
#pragma unroll
    for (int mb = 0; mb < 2; mb++) {
        float il0 = 1.f / lacc[mb][0], il1 = 1.f / lacc[mb][2];
        __half* Ob = Oh + ((size_t)(b * Tn + qb * FM + wid * 32 + mb * 16)) * DMODEL + h * HD;
#pragma unroll
        for (int nt = 0; nt < 16; nt++) {
            int col = nt * 8 + cq2;
            uint32_t w0 = packh2(o[mb][nt][0] * il0, o[mb][nt][1] * il0);
            uint32_t w1 = packh2(o[mb][nt][2] * il1, o[mb][nt][3] * il1);
            *(uint32_t*)(Ob + (size_t)g * DMODEL + col)       = w0;
            *(uint32_t*)(Ob + (size_t)(g + 8) * DMODEL + col) = w1;
        }
    }
}

// ---------------- launch ----------------
extern "C" void kernel_launch(void* const* d_in, const int* in_sizes, int n_in,
                              void* d_out, int out_size) {
    (void)in_sizes; (void)n_in; (void)out_size;
    const float* x  = (const float*)d_in[0];
    const float* wq = (const float*)d_in[1];
    const float* wk = (const float*)d_in[2];
    const float* wv = (const float*)d_in[3];
    const float* wo = (const float*)d_in[4];
    float* out = (float*)d_out;

    __half *xh, *QKVh, *Vh, *Oh, *wTh, *woTh;
    cudaGetSymbolAddress((void**)&xh,   g_xh);
    cudaGetSymbolAddress((void**)&QKVh, g_QKVh);
    cudaGetSymbolAddress((void**)&Vh,   g_Vh);
    cudaGetSymbolAddress((void**)&Oh,   g_Oh);
    cudaGetSymbolAddress((void**)&wTh,  g_wTh);
    cudaGetSymbolAddress((void**)&woTh, g_woTh);

    cudaFuncSetAttribute(flash_mma,   cudaFuncAttributeMaxDynamicSharedMemorySize, FLASH_SMEM);
    cudaFuncSetAttribute(gemm_mma<0>, cudaFuncAttributeMaxDynamicSharedMemorySize, GEMM_SMEM);
    cudaFuncSetAttribute(gemm_mma<1>, cudaFuncAttributeMaxDynamicSharedMemorySize, GEMM_SMEM);

    // prep: weight transposes (fp16 K-major) + x fp16 + invf
    prep_kernel<<<PREP_BLOCKS, 256>>>(x, wq, wk, wv, wo, xh, wTh, woTh);

    // Fused QKV projection; epilogue writes fp16 QKVh + scattered fp16 Vh
    gemm_mma<1><<<dim3(QKVSTR / BN, ROWS / BM), 256, GEMM_SMEM>>>(xh, wTh, QKVh, QKVSTR);

    // RoPE in place on fp16 Q,K
    rope_kernel<<<ROPE_BLOCKS, 256>>>(QKVh);

    // Causal attention (FM=128, 32 rows/warp)
    flash_mma<<<dim3(Tn / FM, NH, Bn), FTHREADS, FLASH_SMEM>>>(QKVh, Vh, Oh);

    // Output projection (fp32 out)
    gemm_mma<0><<<dim3(DMODEL / BN, ROWS / BM), 256, GEMM_SMEM>>>(Oh, woTh, out, DMODEL);
}

// round 14
// speedup vs baseline: 1.0759x; 1.0759x over previous
#include <cuda_runtime.h>
#include <cuda_fp16.h>
#include <math.h>
#include <stdint.h>

// ---------------- problem constants ----------------
#define Bn 2
#define Tn 2048
#define NH 16
#define NKV 4
#define HD 128
#define DMODEL 2048
#define KVDIM 512
#define QKVSTR 3072         // combined QKV row: Q[0:2048) K[2048:2560) V[2560:3072)
#define ROWS 4096           // Bn*Tn
#define GK 2048             // K dim of every GEMM

// ---------------- scratch (__device__ globals) ----------------
__device__ __half g_xh  [(size_t)ROWS * DMODEL];  // fp16 x
__device__ __half g_QKVh[(size_t)ROWS * QKVSTR];  // fp16 Q,K (roped in place); V region unused
__device__ __half g_Vh  [(size_t)ROWS * KVDIM];   // V fp16: [b][kvh][t][d]
__device__ __half g_Oh  [(size_t)ROWS * DMODEL];  // flash output fp16
__device__ __half g_wTh [(size_t)QKVSTR * GK];    // fused [wq;wk;wv] [N,K] K-major fp16
__device__ __half g_woTh[(size_t)DMODEL * GK];
__device__ float  g_invf[64];

// ---------------- PTX helpers (baseline sm_80+ only) ----------------
__device__ __forceinline__ uint32_t smem_u32(const void* p) {
    uint32_t a;
    asm("{ .reg .u64 t; cvta.to.shared.u64 t, %1; cvt.u32.u64 %0, t; }" : "=r"(a) : "l"(p));
    return a;
}
__device__ __forceinline__ uint32_t packh2(float lo, float hi) {   // {lo,hi} fp16x2
    uint32_t r; asm("cvt.rn.f16x2.f32 %0, %1, %2;" : "=r"(r) : "f"(hi), "f"(lo)); return r;
}
__device__ __forceinline__ uint32_t ex2h2(uint32_t x) {            // 2^x on both halves
    uint32_t r; asm("ex2.approx.f16x2 %0, %1;" : "=r"(r) : "r"(x)); return r;
}
__device__ __forceinline__ uint32_t swz(uint32_t off) {   // SW128: bits[6:4] ^= bits[9:7]
    return off ^ ((off >> 3) & 0x70);
}
__device__ __forceinline__ void cp16(uint32_t dst, const void* src) {
    asm volatile("cp.async.cg.shared.global [%0], [%1], 16;" :: "r"(dst), "l"(src) : "memory");
}
#define CP_COMMIT() asm volatile("cp.async.commit_group;" ::: "memory")
#define CP_WAIT(n)  asm volatile("cp.async.wait_group %0;" :: "n"(n) : "memory")

__device__ __forceinline__ void ldsm_x4(uint32_t* r, uint32_t addr) {
    asm volatile("ldmatrix.sync.aligned.m8n8.x4.shared.b16 {%0,%1,%2,%3}, [%4];"
                 : "=r"(r[0]), "=r"(r[1]), "=r"(r[2]), "=r"(r[3]) : "r"(addr));
}
__device__ __forceinline__ void ldsm_x4_trans(uint32_t* r, uint32_t addr) {
    asm volatile("ldmatrix.sync.aligned.m8n8.x4.trans.shared.b16 {%0,%1,%2,%3}, [%4];"
                 : "=r"(r[0]), "=r"(r[1]), "=r"(r[2]), "=r"(r[3]) : "r"(addr));
}
__device__ __forceinline__ void mma_f16(float* d, const uint32_t* a, const uint32_t* b) {
    asm volatile(
        "mma.sync.aligned.m16n8k16.row.col.f32.f16.f16.f32 "
        "{%0,%1,%2,%3}, {%4,%5,%6,%7}, {%8,%9}, {%0,%1,%2,%3};"
        : "+f"(d[0]), "+f"(d[1]), "+f"(d[2]), "+f"(d[3])
        : "r"(a[0]), "r"(a[1]), "r"(a[2]), "r"(a[3]), "r"(b[0]), "r"(b[1]));
}

// ---------------- fused prep kernel ----------------
#define TR_BLOCKS 10240
#define RND_BLOCKS 8192
#define PREP_BLOCKS (TR_BLOCKS + RND_BLOCKS + 1)

__global__ void prep_kernel(const float* __restrict__ x,
                            const float* __restrict__ wq, const float* __restrict__ wk,
                            const float* __restrict__ wv, const float* __restrict__ wo,
                            __half* __restrict__ xh, __half* __restrict__ wTh,
                            __half* __restrict__ woTh) {
    __shared__ float t[32][33];
    int blk = blockIdx.x;
    int tid = threadIdx.x;
    if (blk < TR_BLOCKS) {
        int tx = tid & 31, ty = tid >> 5;
        int bx = blk % 160, kb = blk / 160;
        const float* src; __half* dst; int N;
        if (bx < 64)       { src = wq; dst = wTh;                     N = 2048; }
        else if (bx < 80)  { src = wk; dst = wTh + (size_t)2048 * GK; N = 512;  bx -= 64; }
        else if (bx < 96)  { src = wv; dst = wTh + (size_t)2560 * GK; N = 512;  bx -= 80; }
        else               { src = wo; dst = woTh;                    N = 2048; bx -= 96; }
        int n0 = bx * 32, k0 = kb * 32;
#pragma unroll
        for (int i = ty; i < 32; i += 8)
            t[i][tx] = src[(size_t)(k0 + i) * N + n0 + tx];
        __syncthreads();
#pragma unroll
        for (int i = ty; i < 32; i += 8)
            dst[(size_t)(n0 + i) * GK + k0 + tx] = __float2half_rn(t[tx][i]);
    } else if (blk < TR_BLOCKS + RND_BLOCKS) {
        int i = (blk - TR_BLOCKS) * 256 + tid;
        float4 v = ((const float4*)x)[i];
        uint2 u;
        u.x = packh2(v.x, v.y);
        u.y = packh2(v.z, v.w);
        ((uint2*)xh)[i] = u;
    } else {
        if (tid < 64) g_invf[tid] = (float)exp(-((double)tid / 64.0) * log(10000.0));
    }
}

// ---------------- rope (in-place on fp16 QKVh, Q and K regions) -----------
#define ROPE_TOTQ (ROWS * NH * 64)
#define ROPE_TOTK (ROWS * NKV * 64)
#define ROPE_BLOCKS 20480

__global__ void rope_kernel(__half* __restrict__ QKVh) {
    int idx = blockIdx.x * 256 + threadIdx.x;
    int off; int nheads;
    if (idx < ROPE_TOTQ) { off = 0; nheads = NH; }
    else { idx -= ROPE_TOTQ; off = 2048; nheads = NKV; }
    int d    = idx & 63;
    int rest = idx >> 6;
    int hh   = rest % nheads;
    int row  = rest / nheads;
    int tt   = row & (Tn - 1);
    float ang = (float)tt * g_invf[d];
    float sn, cs;
    sincosf(ang, &sn, &cs);
    __half* p = QKVh + (size_t)row * QKVSTR + off + hh * HD + d;
    float x0 = __half2float(p[0]), x1 = __half2float(p[64]);
    p[0]  = __float2half_rn(x0 * cs - x1 * sn);
    p[64] = __float2half_rn(x1 * cs + x0 * sn);
}

// ---------------- fp16 mma.sync GEMM v5: 64x64 warp tile, BN=256 ----------
// C[M,N] = A[M,2048] @ Bt[N,2048]^T, fp16 in.
// Block 128x256, BK=64 halves (128B rows), 3-stage cp.async, 8 warps (2x4),
// warp tile 64x64, occ 1.
#define BM 128
#define BN 256
#define NSTG 3
#define ASTG 16384            // 128 rows x 128B
#define BSTG 32768            // 256 rows x 128B
#define STG  (ASTG + BSTG)
#define GEMM_SMEM (NSTG * STG)   // 147456
#define KITERS 32

template <int MODE>
__global__ __launch_bounds__(256, 1)
void gemm_mma(const __half* __restrict__ A, const __half* __restrict__ Bt,
              void* __restrict__ Cout, int N) {
    extern __shared__ char dsm[];
    const uint32_t base = smem_u32(dsm);

    const int tid  = threadIdx.x;
    const int wid  = tid >> 5;
    const int lane = tid & 31;
    const int mb   = blockIdx.y * BM;
    const int nb   = blockIdx.x * BN;
    const int wm   = (wid & 1) * 64;
    const int wn   = (wid >> 1) * 64;

    const __half* Ag = A  + (size_t)mb * GK;
    const __half* Bg = Bt + (size_t)nb * GK;

    float acc[4][8][4];
#pragma unroll
    for (int mt = 0; mt < 4; mt++)
#pragma unroll
        for (int nt = 0; nt < 8; nt++)
#pragma unroll
            for (int q = 0; q < 4; q++) acc[mt][nt][q] = 0.f;

    // A: 1024 16B chunks (128 rows x 8); B: 2048 chunks (256 rows x 8)
    auto issue = [&](int buf, int s) {
        uint32_t sa = base + (uint32_t)buf * STG;
        uint32_t sb = sa + ASTG;
        int k0 = s * 64;
#pragma unroll
        for (int i = 0; i < 4; i++) {
            int cc  = tid + i * 256;
            int row = cc >> 3, ch = cc & 7;
            cp16(sa + swz((uint32_t)(row * 128 + ch * 16)),
                 Ag + (size_t)row * GK + k0 + ch * 8);
        }
#pragma unroll
        for (int i = 0; i < 8; i++) {
            int cc  = tid + i * 256;
            int row = cc >> 3, ch = cc & 7;
            cp16(sb + swz((uint32_t)(row * 128 + ch * 16)),
                 Bg + (size_t)row * GK + k0 + ch * 8);
        }
        CP_COMMIT();
    };

    issue(0, 0); issue(1, 1);

    const int a_r  = (lane & 7) + ((lane >> 3) & 1) * 8;
    const int a_kc = (lane >> 4);
    const int b_r  = (lane & 7) + (lane >> 4) * 8;
    const int b_kc = ((lane >> 3) & 1);

    int st = 0, stp = 2;
    for (int s = 0; s < KITERS; s++) {
        if (s + 2 < KITERS) CP_WAIT(1); else CP_WAIT(0);
        __syncthreads();
        if (s + 2 < KITERS) issue(stp, s + 2);

        uint32_t sa = base + (uint32_t)st * STG + (uint32_t)(wm * 128);
        uint32_t sb = base + (uint32_t)st * STG + ASTG + (uint32_t)(wn * 128);

#pragma unroll
        for (int ks = 0; ks < 4; ks++) {       // 4 x k16 per BK=64
            uint32_t afr[4][4];
            uint32_t bfr[8][2];
#pragma unroll
            for (int mt = 0; mt < 4; mt++)
                ldsm_x4(afr[mt], sa + swz((uint32_t)((mt * 16 + a_r) * 128 + (2 * ks + a_kc) * 16)));
#pragma unroll
            for (int np = 0; np < 4; np++) {
                uint32_t tmp[4];
                ldsm_x4(tmp, sb + swz((uint32_t)((np * 16 + b_r) * 128 + (2 * ks + b_kc) * 16)));
                bfr[np * 2][0] = tmp[0]; bfr[np * 2][1] = tmp[1];
                bfr[np * 2 + 1][0] = tmp[2]; bfr[np * 2 + 1][1] = tmp[3];
            }
#pragma unroll
            for (int mt = 0; mt < 4; mt++)
#pragma unroll
                for (int nt = 0; nt < 8; nt++)
                    mma_f16(acc[mt][nt], afr[mt], bfr[nt]);
        }
        st  = (st  == NSTG - 1) ? 0 : st + 1;
        stp = (stp == NSTG - 1) ? 0 : stp + 1;
    }

    const int g = lane >> 2;
    const int cq = (lane & 3) * 2;
#pragma unroll
    for (int mt = 0; mt < 4; mt++) {
        int row0 = mb + wm + mt * 16 + g;
#pragma unroll
        for (int nt = 0; nt < 8; nt++) {
            int col = nb + wn + nt * 8 + cq;
            if (MODE == 0) {
                float* C = (float*)Cout;
                *(float2*)(C + (size_t)row0 * N + col)       = make_float2(acc[mt][nt][0], acc[mt][nt][1]);
                *(float2*)(C + (size_t)(row0 + 8) * N + col) = make_float2(acc[mt][nt][2], acc[mt][nt][3]);
            } else {
                uint32_t w0 = packh2(acc[mt][nt][0], acc[mt][nt][1]);
                uint32_t w1 = packh2(acc[mt][nt][2], acc[mt][nt][3]);
                if (col < 2560) {
                    __half* C = (__half*)Cout;
                    *(uint32_t*)(C + (size_t)row0 * QKVSTR + col)       = w0;
                    *(uint32_t*)(C + (size_t)(row0 + 8) * QKVSTR + col) = w1;
                } else {
                    int rel = col - 2560;
                    int kvh = rel >> 7, d = rel & 127;
                    int b0 = row0 >> 11, t0 = row0 & (Tn - 1);
                    int b1 = (row0 + 8) >> 11, t1 = (row0 + 8) & (Tn - 1);
                    *(uint32_t*)(g_Vh + (((size_t)(b0 * NKV + kvh) * Tn + t0) * HD + d)) = w0;
                    *(uint32_t*)(g_Vh + (((size_t)(b1 * NKV + kvh) * Tn + t1) * HD + d)) = w1;
                }
            }
        }
    }
}

// ---------------- flash attention (exact R12 config: best measured) -------
#define FM 64
#define FN 64
#define KVBUF 32768
#define FLASH_SMEM (16384 + 2 * KVBUF)   // 81920
#define FTHREADS 128

__global__ __launch_bounds__(FTHREADS, 2)
void flash_mma(const __half* __restrict__ QKVh, const __half* __restrict__ Vh,
               __half* __restrict__ Oh) {
    extern __shared__ float sm[];
    const uint32_t base = smem_u32(sm);
    const int tid = threadIdx.x, wid = tid >> 5, lane = tid & 31;
    const int qb = (Tn / FM - 1) - blockIdx.x;   // heavy blocks first
    const int h = blockIdx.y, b = blockIdx.z;
    const int kvh = h >> 2;
    const int nkt = qb + 1;

    const __half* Qg = QKVh + ((size_t)(b * Tn + qb * FM)) * QKVSTR + h * HD;
    const __half* Kg = QKVh + ((size_t)(b * Tn)) * QKVSTR + 2048 + kvh * HD;
    const __half* Vg = Vh + ((size_t)(b * NKV + kvh)) * Tn * HD;

    // ---- Q tile: 1024 16B chunks
#pragma unroll
    for (int i = 0; i < 8; i++) {
        int f = tid + i * FTHREADS;
        int qr = f >> 4, ch = f & 15;
        cp16(base + (uint32_t)((ch >> 3) * 8192) + swz((uint32_t)(qr * 128 + (ch & 7) * 16)),
             Qg + (size_t)qr * QKVSTR + ch * 8);
    }

    auto kv_issue = [&](int kt) {
        uint32_t kb = base + 16384u + (uint32_t)(kt & 1) * KVBUF;
        uint32_t vb = kb + 16384u;
        const __half* Ksrc = Kg + (size_t)(kt * FN) * QKVSTR;
        const __half* Vsrc = Vg + (size_t)(kt * FN) * HD;
#pragma unroll
        for (int i = 0; i < 8; i++) {
            int f = tid + i * FTHREADS;
            int kr = f >> 4, ch = f & 15;
            cp16(kb + (uint32_t)((ch >> 3) * 8192) + swz((uint32_t)(kr * 128 + (ch & 7) * 16)),
                 Ksrc + (size_t)kr * QKVSTR + ch * 8);
        }
#pragma unroll
        for (int i = 0; i < 8; i++) {
            int f = tid + i * FTHREADS;
            int key = f >> 4, ch = f & 15;
            cp16(vb + (uint32_t)((ch >> 3) * 8192) + swz((uint32_t)(key * 128 + (ch & 7) * 16)),
                 Vsrc + key * HD + ch * 8);
        }
        CP_COMMIT();
    };

    const int a_r  = (lane & 7) + ((lane >> 3) & 1) * 8;
    const int a_kc = lane >> 4;
    const int b_r  = (lane & 7) + (lane >> 4) * 8;
    const int b_kc = (lane >> 3) & 1;
    const int g    = lane >> 2;
    const int cq2  = (lane & 3) * 2;
    const int vrow = lane & 7;
    const int vmi  = lane >> 3;
    const float scale2 = 0.08838834764831843f * 1.4426950408889634f;
    const uint32_t ONESx2 = 0x3C003C00u;
    const uint32_t bones[2] = {ONESx2, ONESx2};

    float o[16][4];
#pragma unroll
    for (int nt = 0; nt < 16; nt++)
#pragma unroll
        for (int q = 0; q < 4; q++) o[nt][q] = 0.f;
    float lacc[4] = {0.f, 0.f, 0.f, 0.f};
    float m0 = -1e30f, m1 = -1e30f;

    kv_issue(0);

    for (int kt = 0; kt < nkt; kt++) {
        __syncthreads();
        if (kt + 1 < nkt) { kv_issue(kt + 1); CP_WAIT(1); }
        else              { CP_WAIT(0); }
        __syncthreads();

        uint32_t kb = base + 16384u + (uint32_t)(kt & 1) * KVBUF;
        uint32_t vb = kb + 16384u;

        // ---- S = Q @ K^T
        float sacc[8][4];
#pragma unroll
        for (int nt = 0; nt < 8; nt++)
#pragma unroll
            for (int q = 0; q < 4; q++) sacc[nt][q] = 0.f;

#pragma unroll
        for (int ks = 0; ks < 8; ks++) {
            uint32_t af[4];
            ldsm_x4(af, base + (uint32_t)((ks >> 2) * 8192)
                        + swz((uint32_t)((wid * 16 + a_r) * 128 + ((ks & 3) * 2 + a_kc) * 16)));
            uint32_t bf[8][2];
#pragma unroll
            for (int np = 0; np < 4; np++) {
                uint32_t tmp[4];
                ldsm_x4(tmp, kb + (uint32_t)((ks >> 2) * 8192)
                             + swz((uint32_t)((np * 16 + b_r) * 128 + ((ks & 3) * 2 + b_kc) * 16)));
                bf[np * 2][0] = tmp[0]; bf[np * 2][1] = tmp[1];
                bf[np * 2 + 1][0] = tmp[2]; bf[np * 2 + 1][1] = tmp[3];
            }
#pragma unroll
            for (int nt = 0; nt < 8; nt++) mma_f16(sacc[nt], af, bf[nt]);
        }

        // ---- scale + causal mask (diagonal tile only)
        if (kt == qb) {
            int rl0 = wid * 16 + g, rl1 = rl0 + 8;
#pragma unroll
            for (int nt = 0; nt < 8; nt++) {
                int kc0 = nt * 8 + cq2;
                sacc[nt][0] = (kc0     > rl0) ? -1e30f : sacc[nt][0] * scale2;
                sacc[nt][1] = (kc0 + 1 > rl0) ? -1e30f : sacc[nt][1] * scale2;
                sacc[nt][2] = (kc0     > rl1) ? -1e30f : sacc[nt][2] * scale2;
                sacc[nt][3] = (kc0 + 1 > rl1) ? -1e30f : sacc[nt][3] * scale2;
            }
        } else {
#pragma unroll
            for (int nt = 0; nt < 8; nt++)
#pragma unroll
                for (int q = 0; q < 4; q++) sacc[nt][q] *= scale2;
        }

        // ---- row max + alpha
        float mx0 = -1e30f, mx1 = -1e30f;
#pragma unroll
        for (int nt = 0; nt < 8; nt++) {
            mx0 = fmaxf(mx0, fmaxf(sacc[nt][0], sacc[nt][1]));
            mx1 = fmaxf(mx1, fmaxf(sacc[nt][2], sacc[nt][3]));
        }
        mx0 = fmaxf(mx0, __shfl_xor_sync(0xffffffffu, mx0, 1));
        mx0 = fmaxf(mx0, __shfl_xor_sync(0xffffffffu, mx0, 2));
        mx1 = fmaxf(mx1, __shfl_xor_sync(0xffffffffu, mx1, 1));
        mx1 = fmaxf(mx1, __shfl_xor_sync(0xffffffffu, mx1, 2));
        float nm0 = fmaxf(m0, mx0), nm1 = fmaxf(m1, mx1);
        float al0 = exp2f(m0 - nm0), al1 = exp2f(m1 - nm1);
        m0 = nm0; m1 = nm1;

        // ---- P = 2^(s-nm) in fp16x2; pf[kc] IS the PV A-fragment
        uint32_t pf[4][4];
#pragma unroll
        for (int kc = 0; kc < 4; kc++) {
            pf[kc][0] = ex2h2(packh2(sacc[2 * kc][0] - nm0,     sacc[2 * kc][1] - nm0));
            pf[kc][1] = ex2h2(packh2(sacc[2 * kc][2] - nm1,     sacc[2 * kc][3] - nm1));
            pf[kc][2] = ex2h2(packh2(sacc[2 * kc + 1][0] - nm0, sacc[2 * kc + 1][1] - nm0));
            pf[kc][3] = ex2h2(packh2(sacc[2 * kc + 1][2] - nm1, sacc[2 * kc + 1][3] - nm1));
        }

        // ---- rescale O + l accumulators
#pragma unroll
        for (int nt = 0; nt < 16; nt++) {
            o[nt][0] *= al0; o[nt][1] *= al0;
            o[nt][2] *= al1; o[nt][3] *= al1;
        }
        lacc[0] *= al0; lacc[1] *= al0;
        lacc[2] *= al1; lacc[3] *= al1;

        // ---- l += P @ ones
#pragma unroll
        for (int kc = 0; kc < 4; kc++) mma_f16(lacc, pf[kc], bones);

        // ---- O += P @ V
#pragma unroll
        for (int kc = 0; kc < 4; kc++) {
            int vkey = kc * 16 + (vmi & 1) * 8 + vrow;
#pragma unroll
            for (int np = 0; np < 16; np += 2) {
                int npp = np + (vmi >> 1);
                uint32_t tmp[4];
                ldsm_x4_trans(tmp, vb + (uint32_t)((npp >> 3) * 8192)
                                      + swz((uint32_t)(vkey * 128 + (npp & 7) * 16)));
                mma_f16(o[np],     pf[kc], tmp);
                mma_f16(o[np + 1], pf[kc], tmp + 2);
            }
        }
    }

    // ---- epilogue
    float il0 = 1.f / lacc[0], il1 = 1.f / lacc[2];
    __half* Ob = Oh + ((size_t)(b * Tn + qb * FM + wid * 16)) * DMODEL + h * HD;
#pragma unroll
    for (int nt = 0; nt < 16; nt++) {
        int col = nt * 8 + cq2;
        uint32_t w0 = packh2(o[nt][0] * il0, o[nt][1] * il0);
        uint32_t w1 = packh2(o[nt][2] * il1, o[nt][3] * il1);
        *(uint32_t*)(Ob + (size_t)g * DMODEL + col)       = w0;
        *(uint32_t*)(Ob + (size_t)(g + 8) * DMODEL + col) = w1;
    }
}

// ---------------- launch ----------------
extern "C" void kernel_launch(void* const* d_in, const int* in_sizes, int n_in,
                              void* d_out, int out_size) {
    (void)in_sizes; (void)n_in; (void)out_size;
    const float* x  = (const float*)d_in[0];
    const float* wq = (const float*)d_in[1];
    const float* wk = (const float*)d_in[2];
    const float* wv = (const float*)d_in[3];
    const float* wo = (const float*)d_in[4];
    float* out = (float*)d_out;

    __half *xh, *QKVh, *Vh, *Oh, *wTh, *woTh;
    cudaGetSymbolAddress((void**)&xh,   g_xh);
    cudaGetSymbolAddress((void**)&QKVh, g_QKVh);
    cudaGetSymbolAddress((void**)&Vh,   g_Vh);
    cudaGetSymbolAddress((void**)&Oh,   g_Oh);
    cudaGetSymbolAddress((void**)&wTh,  g_wTh);
    cudaGetSymbolAddress((void**)&woTh, g_woTh);

    cudaFuncSetAttribute(flash_mma,   cudaFuncAttributeMaxDynamicSharedMemorySize, FLASH_SMEM);
    cudaFuncSetAttribute(gemm_mma<0>, cudaFuncAttributeMaxDynamicSharedMemorySize, GEMM_SMEM);
    cudaFuncSetAttribute(gemm_mma<1>, cudaFuncAttributeMaxDynamicSharedMemorySize, GEMM_SMEM);

    // prep: weight transposes (fp16 K-major) + x fp16 + invf
    prep_kernel<<<PREP_BLOCKS, 256>>>(x, wq, wk, wv, wo, xh, wTh, woTh);

    // Fused QKV projection; epilogue writes fp16 QKVh + scattered fp16 Vh
    gemm_mma<1><<<dim3(QKVSTR / BN, ROWS / BM), 256, GEMM_SMEM>>>(xh, wTh, QKVh, QKVSTR);

    // RoPE in place on fp16 Q,K
    rope_kernel<<<ROPE_BLOCKS, 256>>>(QKVh);

    // Causal attention (R12 config)
    flash_mma<<<dim3(Tn / FM, NH, Bn), FTHREADS, FLASH_SMEM>>>(QKVh, Vh, Oh);

    // Output projection (fp32 out)
    gemm_mma<0><<<dim3(DMODEL / BN, ROWS / BM), 256, GEMM_SMEM>>>(Oh, woTh, out, DMODEL);
}

// round 15
// speedup vs baseline: 1.0839x; 1.0074x over previous
#include <cuda_runtime.h>
#include <cuda_fp16.h>
#include <math.h>
#include <stdint.h>

// ---------------- problem constants ----------------
#define Bn 2
#define Tn 2048
#define NH 16
#define NKV 4
#define HD 128
#define DMODEL 2048
#define KVDIM 512
#define QKVSTR 3072         // combined QKV row: Q[0:2048) K[2048:2560) V[2560:3072)
#define ROWS 4096           // Bn*Tn
#define GK 2048             // K dim of every GEMM

// ---------------- scratch (__device__ globals) ----------------
__device__ __half g_xh  [(size_t)ROWS * DMODEL];  // fp16 x
__device__ __half g_QKVh[(size_t)ROWS * QKVSTR];  // fp16 Q,K (roped in place); V region unused
__device__ __half g_Vh  [(size_t)ROWS * KVDIM];   // V fp16: [b][kvh][t][d]
__device__ __half g_Oh  [(size_t)ROWS * DMODEL];  // flash output fp16
__device__ __half g_wTh [(size_t)QKVSTR * GK];    // fused [wq;wk;wv] [N,K] K-major fp16
__device__ __half g_woTh[(size_t)DMODEL * GK];
__device__ float  g_invf[64];

// ---------------- PTX helpers (baseline sm_80+ only) ----------------
__device__ __forceinline__ uint32_t smem_u32(const void* p) {
    uint32_t a;
    asm("{ .reg .u64 t; cvta.to.shared.u64 t, %1; cvt.u32.u64 %0, t; }" : "=r"(a) : "l"(p));
    return a;
}
__device__ __forceinline__ uint32_t packh2(float lo, float hi) {   // {lo,hi} fp16x2
    uint32_t r; asm("cvt.rn.f16x2.f32 %0, %1, %2;" : "=r"(r) : "f"(hi), "f"(lo)); return r;
}
__device__ __forceinline__ uint32_t ex2h2(uint32_t x) {            // 2^x on both halves
    uint32_t r; asm("ex2.approx.f16x2 %0, %1;" : "=r"(r) : "r"(x)); return r;
}
__device__ __forceinline__ uint32_t swz(uint32_t off) {   // SW128: bits[6:4] ^= bits[9:7]
    return off ^ ((off >> 3) & 0x70);
}
__device__ __forceinline__ void cp16(uint32_t dst, const void* src) {
    asm volatile("cp.async.cg.shared.global [%0], [%1], 16;" :: "r"(dst), "l"(src) : "memory");
}
#define CP_COMMIT() asm volatile("cp.async.commit_group;" ::: "memory")
#define CP_WAIT(n)  asm volatile("cp.async.wait_group %0;" :: "n"(n) : "memory")

__device__ __forceinline__ void ldsm_x4(uint32_t* r, uint32_t addr) {
    asm volatile("ldmatrix.sync.aligned.m8n8.x4.shared.b16 {%0,%1,%2,%3}, [%4];"
                 : "=r"(r[0]), "=r"(r[1]), "=r"(r[2]), "=r"(r[3]) : "r"(addr));
}
__device__ __forceinline__ void ldsm_x4_trans(uint32_t* r, uint32_t addr) {
    asm volatile("ldmatrix.sync.aligned.m8n8.x4.trans.shared.b16 {%0,%1,%2,%3}, [%4];"
                 : "=r"(r[0]), "=r"(r[1]), "=r"(r[2]), "=r"(r[3]) : "r"(addr));
}
__device__ __forceinline__ void mma_f16(float* d, const uint32_t* a, const uint32_t* b) {
    asm volatile(
        "mma.sync.aligned.m16n8k16.row.col.f32.f16.f16.f32 "
        "{%0,%1,%2,%3}, {%4,%5,%6,%7}, {%8,%9}, {%0,%1,%2,%3};"
        : "+f"(d[0]), "+f"(d[1]), "+f"(d[2]), "+f"(d[3])
        : "r"(a[0]), "r"(a[1]), "r"(a[2]), "r"(a[3]), "r"(b[0]), "r"(b[1]));
}

// ---------------- fused prep kernel ----------------
#define TR_BLOCKS 10240
#define RND_BLOCKS 8192
#define PREP_BLOCKS (TR_BLOCKS + RND_BLOCKS + 1)

__global__ void prep_kernel(const float* __restrict__ x,
                            const float* __restrict__ wq, const float* __restrict__ wk,
                            const float* __restrict__ wv, const float* __restrict__ wo,
                            __half* __restrict__ xh, __half* __restrict__ wTh,
                            __half* __restrict__ woTh) {
    __shared__ float t[32][33];
    int blk = blockIdx.x;
    int tid = threadIdx.x;
    if (blk < TR_BLOCKS) {
        int tx = tid & 31, ty = tid >> 5;
        int bx = blk % 160, kb = blk / 160;
        const float* src; __half* dst; int N;
        if (bx < 64)       { src = wq; dst = wTh;                     N = 2048; }
        else if (bx < 80)  { src = wk; dst = wTh + (size_t)2048 * GK; N = 512;  bx -= 64; }
        else if (bx < 96)  { src = wv; dst = wTh + (size_t)2560 * GK; N = 512;  bx -= 80; }
        else               { src = wo; dst = woTh;                    N = 2048; bx -= 96; }
        int n0 = bx * 32, k0 = kb * 32;
#pragma unroll
        for (int i = ty; i < 32; i += 8)
            t[i][tx] = src[(size_t)(k0 + i) * N + n0 + tx];
        __syncthreads();
#pragma unroll
        for (int i = ty; i < 32; i += 8)
            dst[(size_t)(n0 + i) * GK + k0 + tx] = __float2half_rn(t[tx][i]);
    } else if (blk < TR_BLOCKS + RND_BLOCKS) {
        int i = (blk - TR_BLOCKS) * 256 + tid;
        float4 v = ((const float4*)x)[i];
        uint2 u;
        u.x = packh2(v.x, v.y);
        u.y = packh2(v.z, v.w);
        ((uint2*)xh)[i] = u;
    } else {
        if (tid < 64) g_invf[tid] = (float)exp(-((double)tid / 64.0) * log(10000.0));
    }
}

// ---------------- rope (in-place on fp16 QKVh, Q and K regions) -----------
#define ROPE_TOTQ (ROWS * NH * 64)
#define ROPE_TOTK (ROWS * NKV * 64)
#define ROPE_BLOCKS 20480

__global__ void rope_kernel(__half* __restrict__ QKVh) {
    int idx = blockIdx.x * 256 + threadIdx.x;
    int off; int nheads;
    if (idx < ROPE_TOTQ) { off = 0; nheads = NH; }
    else { idx -= ROPE_TOTQ; off = 2048; nheads = NKV; }
    int d    = idx & 63;
    int rest = idx >> 6;
    int hh   = rest % nheads;
    int row  = rest / nheads;
    int tt   = row & (Tn - 1);
    float ang = (float)tt * g_invf[d];
    float sn, cs;
    sincosf(ang, &sn, &cs);
    __half* p = QKVh + (size_t)row * QKVSTR + off + hh * HD + d;
    float x0 = __half2float(p[0]), x1 = __half2float(p[64]);
    p[0]  = __float2half_rn(x0 * cs - x1 * sn);
    p[64] = __float2half_rn(x1 * cs + x0 * sn);
}

// ---------------- fp16 mma.sync GEMM (R12 config: occ 2, 128x128) ---------
#define BM 128
#define BN 128
#define NSTG 3
#define ASTG 16384
#define BSTG 16384
#define STG  (ASTG + BSTG)
#define GEMM_SMEM (NSTG * STG)   // 98304
#define KITERS 32

template <int MODE>
__global__ __launch_bounds__(256, 2)
void gemm_mma(const __half* __restrict__ A, const __half* __restrict__ Bt,
              void* __restrict__ Cout, int N) {
    extern __shared__ char dsm[];
    const uint32_t base = smem_u32(dsm);

    const int tid  = threadIdx.x;
    const int wid  = tid >> 5;
    const int lane = tid & 31;
    const int mb   = blockIdx.y * BM;
    const int nb   = blockIdx.x * BN;
    const int wm   = (wid & 1) * 64;
    const int wn   = (wid >> 1) * 32;

    const __half* Ag = A  + (size_t)mb * GK;
    const __half* Bg = Bt + (size_t)nb * GK;

    float acc[4][4][4];
#pragma unroll
    for (int mt = 0; mt < 4; mt++)
#pragma unroll
        for (int nt = 0; nt < 4; nt++)
#pragma unroll
            for (int q = 0; q < 4; q++) acc[mt][nt][q] = 0.f;

    auto issue = [&](int buf, int s) {
        uint32_t sa = base + (uint32_t)buf * STG;
        uint32_t sb = sa + ASTG;
        int k0 = s * 64;
#pragma unroll
        for (int i = 0; i < 4; i++) {
            int cc  = tid + i * 256;
            int row = cc >> 3, ch = cc & 7;
            uint32_t off = swz((uint32_t)(row * 128 + ch * 16));
            cp16(sa + off, Ag + (size_t)row * GK + k0 + ch * 8);
            cp16(sb + off, Bg + (size_t)row * GK + k0 + ch * 8);
        }
        CP_COMMIT();
    };

    issue(0, 0); issue(1, 1);

    const int a_r  = (lane & 7) + ((lane >> 3) & 1) * 8;
    const int a_kc = (lane >> 4);
    const int b_r  = (lane & 7) + (lane >> 4) * 8;
    const int b_kc = ((lane >> 3) & 1);

    int st = 0, stp = 2;
    for (int s = 0; s < KITERS; s++) {
        if (s + 2 < KITERS) CP_WAIT(1); else CP_WAIT(0);
        __syncthreads();
        if (s + 2 < KITERS) issue(stp, s + 2);

        uint32_t sa = base + (uint32_t)st * STG + (uint32_t)(wm * 128);
        uint32_t sb = base + (uint32_t)st * STG + ASTG + (uint32_t)(wn * 128);

#pragma unroll
        for (int ks = 0; ks < 4; ks++) {
            uint32_t afr[4][4];
            uint32_t bfr[4][2];
#pragma unroll
            for (int mt = 0; mt < 4; mt++)
                ldsm_x4(afr[mt], sa + swz((uint32_t)((mt * 16 + a_r) * 128 + (2 * ks + a_kc) * 16)));
            {
                uint32_t tmp[4];
                ldsm_x4(tmp, sb + swz((uint32_t)((b_r) * 128 + (2 * ks + b_kc) * 16)));
                bfr[0][0] = tmp[0]; bfr[0][1] = tmp[1];
                bfr[1][0] = tmp[2]; bfr[1][1] = tmp[3];
                ldsm_x4(tmp, sb + swz((uint32_t)((16 + b_r) * 128 + (2 * ks + b_kc) * 16)));
                bfr[2][0] = tmp[0]; bfr[2][1] = tmp[1];
                bfr[3][0] = tmp[2]; bfr[3][1] = tmp[3];
            }
#pragma unroll
            for (int mt = 0; mt < 4; mt++)
#pragma unroll
                for (int nt = 0; nt < 4; nt++)
                    mma_f16(acc[mt][nt], afr[mt], bfr[nt]);
        }
        st  = (st  == NSTG - 1) ? 0 : st + 1;
        stp = (stp == NSTG - 1) ? 0 : stp + 1;
    }

    const int g = lane >> 2;
    const int cq = (lane & 3) * 2;
#pragma unroll
    for (int mt = 0; mt < 4; mt++) {
        int row0 = mb + wm + mt * 16 + g;
#pragma unroll
        for (int nt = 0; nt < 4; nt++) {
            int col = nb + wn + nt * 8 + cq;
            if (MODE == 0) {
                float* C = (float*)Cout;
                *(float2*)(C + (size_t)row0 * N + col)       = make_float2(acc[mt][nt][0], acc[mt][nt][1]);
                *(float2*)(C + (size_t)(row0 + 8) * N + col) = make_float2(acc[mt][nt][2], acc[mt][nt][3]);
            } else {
                uint32_t w0 = packh2(acc[mt][nt][0], acc[mt][nt][1]);
                uint32_t w1 = packh2(acc[mt][nt][2], acc[mt][nt][3]);
                if (col < 2560) {
                    __half* C = (__half*)Cout;
                    *(uint32_t*)(C + (size_t)row0 * QKVSTR + col)       = w0;
                    *(uint32_t*)(C + (size_t)(row0 + 8) * QKVSTR + col) = w1;
                } else {
                    int rel = col - 2560;
                    int kvh = rel >> 7, d = rel & 127;
                    int b0 = row0 >> 11, t0 = row0 & (Tn - 1);
                    int b1 = (row0 + 8) >> 11, t1 = (row0 + 8) & (Tn - 1);
                    *(uint32_t*)(g_Vh + (((size_t)(b0 * NKV + kvh) * Tn + t0) * HD + d)) = w0;
                    *(uint32_t*)(g_Vh + (((size_t)(b1 * NKV + kvh) * Tn + t1) * HD + d)) = w1;
                }
            }
        }
    }
}

// ---------------- flash attention: persistent CTAs, balanced jobs ---------
// 296 CTAs (2/SM); job j (heavy-first) -> qb = 31 - j/32, (h,b) = j%32.
// Per-job core = R12 config (FM=64, 128 threads, fp16, ex2h2, mma row-sums).
#define FM 64
#define FN 64
#define KVBUF 32768
#define FLASH_SMEM (16384 + 2 * KVBUF)   // 81920
#define FTHREADS 128
#define NJOBS 1024
#define NPERS 296

__global__ __launch_bounds__(FTHREADS, 2)
void flash_mma(const __half* __restrict__ QKVh, const __half* __restrict__ Vh,
               __half* __restrict__ Oh) {
    extern __shared__ float sm[];
    const uint32_t base = smem_u32(sm);
    const int tid = threadIdx.x, wid = tid >> 5, lane = tid & 31;

    const int a_r  = (lane & 7) + ((lane >> 3) & 1) * 8;
    const int a_kc = lane >> 4;
    const int b_r  = (lane & 7) + (lane >> 4) * 8;
    const int b_kc = (lane >> 3) & 1;
    const int g    = lane >> 2;
    const int cq2  = (lane & 3) * 2;
    const int vrow = lane & 7;
    const int vmi  = lane >> 3;
    const float scale2 = 0.08838834764831843f * 1.4426950408889634f;
    const uint32_t ONESx2 = 0x3C003C00u;
    const uint32_t bones[2] = {ONESx2, ONESx2};

    for (int job = blockIdx.x; job < NJOBS; job += NPERS) {
        const int qb = 31 - (job >> 5);
        const int hb = job & 31;
        const int h = hb & 15, b = hb >> 4;
        const int kvh = h >> 2;
        const int nkt = qb + 1;

        const __half* Qg = QKVh + ((size_t)(b * Tn + qb * FM)) * QKVSTR + h * HD;
        const __half* Kg = QKVh + ((size_t)(b * Tn)) * QKVSTR + 2048 + kvh * HD;
        const __half* Vg = Vh + ((size_t)(b * NKV + kvh)) * Tn * HD;

        __syncthreads();   // smem safe to reuse (prev job fully consumed)

        // ---- Q tile: 1024 16B chunks
#pragma unroll
        for (int i = 0; i < 8; i++) {
            int f = tid + i * FTHREADS;
            int qr = f >> 4, ch = f & 15;
            cp16(base + (uint32_t)((ch >> 3) * 8192) + swz((uint32_t)(qr * 128 + (ch & 7) * 16)),
                 Qg + (size_t)qr * QKVSTR + ch * 8);
        }

        auto kv_issue = [&](int kt) {
            uint32_t kb = base + 16384u + (uint32_t)(kt & 1) * KVBUF;
            uint32_t vb = kb + 16384u;
            const __half* Ksrc = Kg + (size_t)(kt * FN) * QKVSTR;
            const __half* Vsrc = Vg + (size_t)(kt * FN) * HD;
#pragma unroll
            for (int i = 0; i < 8; i++) {
                int f = tid + i * FTHREADS;
                int kr = f >> 4, ch = f & 15;
                cp16(kb + (uint32_t)((ch >> 3) * 8192) + swz((uint32_t)(kr * 128 + (ch & 7) * 16)),
                     Ksrc + (size_t)kr * QKVSTR + ch * 8);
            }
#pragma unroll
            for (int i = 0; i < 8; i++) {
                int f = tid + i * FTHREADS;
                int key = f >> 4, ch = f & 15;
                cp16(vb + (uint32_t)((ch >> 3) * 8192) + swz((uint32_t)(key * 128 + (ch & 7) * 16)),
                     Vsrc + key * HD + ch * 8);
            }
            CP_COMMIT();
        };

        float o[16][4];
#pragma unroll
        for (int nt = 0; nt < 16; nt++)
#pragma unroll
            for (int q = 0; q < 4; q++) o[nt][q] = 0.f;
        float lacc[4] = {0.f, 0.f, 0.f, 0.f};
        float m0 = -1e30f, m1 = -1e30f;

        kv_issue(0);

        for (int kt = 0; kt < nkt; kt++) {
            __syncthreads();
            if (kt + 1 < nkt) { kv_issue(kt + 1); CP_WAIT(1); }
            else              { CP_WAIT(0); }
            __syncthreads();

            uint32_t kb = base + 16384u + (uint32_t)(kt & 1) * KVBUF;
            uint32_t vb = kb + 16384u;

            // ---- S = Q @ K^T
            float sacc[8][4];
#pragma unroll
            for (int nt = 0; nt < 8; nt++)
#pragma unroll
                for (int q = 0; q < 4; q++) sacc[nt][q] = 0.f;

#pragma unroll
            for (int ks = 0; ks < 8; ks++) {
                uint32_t af[4];
                ldsm_x4(af, base + (uint32_t)((ks >> 2) * 8192)
                            + swz((uint32_t)((wid * 16 + a_r) * 128 + ((ks & 3) * 2 + a_kc) * 16)));
                uint32_t bf[8][2];
#pragma unroll
                for (int np = 0; np < 4; np++) {
                    uint32_t tmp[4];
                    ldsm_x4(tmp, kb + (uint32_t)((ks >> 2) * 8192)
                                 + swz((uint32_t)((np * 16 + b_r) * 128 + ((ks & 3) * 2 + b_kc) * 16)));
                    bf[np * 2][0] = tmp[0]; bf[np * 2][1] = tmp[1];
                    bf[np * 2 + 1][0] = tmp[2]; bf[np * 2 + 1][1] = tmp[3];
                }
#pragma unroll
                for (int nt = 0; nt < 8; nt++) mma_f16(sacc[nt], af, bf[nt]);
            }

            // ---- scale + causal mask (diagonal tile only)
            if (kt == qb) {
                int rl0 = wid * 16 + g, rl1 = rl0 + 8;
#pragma unroll
                for (int nt = 0; nt < 8; nt++) {
                    int kc0 = nt * 8 + cq2;
                    sacc[nt][0] = (kc0     > rl0) ? -1e30f : sacc[nt][0] * scale2;
                    sacc[nt][1] = (kc0 + 1 > rl0) ? -1e30f : sacc[nt][1] * scale2;
                    sacc[nt][2] = (kc0     > rl1) ? -1e30f : sacc[nt][2] * scale2;
                    sacc[nt][3] = (kc0 + 1 > rl1) ? -1e30f : sacc[nt][3] * scale2;
                }
            } else {
#pragma unroll
                for (int nt = 0; nt < 8; nt++)
#pragma unroll
                    for (int q = 0; q < 4; q++) sacc[nt][q] *= scale2;
            }

            // ---- row max + alpha
            float mx0 = -1e30f, mx1 = -1e30f;
#pragma unroll
            for (int nt = 0; nt < 8; nt++) {
                mx0 = fmaxf(mx0, fmaxf(sacc[nt][0], sacc[nt][1]));
                mx1 = fmaxf(mx1, fmaxf(sacc[nt][2], sacc[nt][3]));
            }
            mx0 = fmaxf(mx0, __shfl_xor_sync(0xffffffffu, mx0, 1));
            mx0 = fmaxf(mx0, __shfl_xor_sync(0xffffffffu, mx0, 2));
            mx1 = fmaxf(mx1, __shfl_xor_sync(0xffffffffu, mx1, 1));
            mx1 = fmaxf(mx1, __shfl_xor_sync(0xffffffffu, mx1, 2));
            float nm0 = fmaxf(m0, mx0), nm1 = fmaxf(m1, mx1);
            float al0 = exp2f(m0 - nm0), al1 = exp2f(m1 - nm1);
            m0 = nm0; m1 = nm1;

            // ---- P = 2^(s-nm) in fp16x2; pf[kc] IS the PV A-fragment
            uint32_t pf[4][4];
#pragma unroll
            for (int kc = 0; kc < 4; kc++) {
                pf[kc][0] = ex2h2(packh2(sacc[2 * kc][0] - nm0,     sacc[2 * kc][1] - nm0));
                pf[kc][1] = ex2h2(packh2(sacc[2 * kc][2] - nm1,     sacc[2 * kc][3] - nm1));
                pf[kc][2] = ex2h2(packh2(sacc[2 * kc + 1][0] - nm0, sacc[2 * kc + 1][1] - nm0));
                pf[kc][3] = ex2h2(packh2(sacc[2 * kc + 1][2] - nm1, sacc[2 * kc + 1][3] - nm1));
            }

            // ---- rescale O + l accumulators
#pragma unroll
            for (int nt = 0; nt < 16; nt++) {
                o[nt][0] *= al0; o[nt][1] *= al0;
                o[nt][2] *= al1; o[nt][3] *= al1;
            }
            lacc[0] *= al0; lacc[1] *= al0;
            lacc[2] *= al1; lacc[3] *= al1;

            // ---- l += P @ ones
#pragma unroll
            for (int kc = 0; kc < 4; kc++) mma_f16(lacc, pf[kc], bones);

            // ---- O += P @ V
#pragma unroll
            for (int kc = 0; kc < 4; kc++) {
                int vkey = kc * 16 + (vmi & 1) * 8 + vrow;
#pragma unroll
                for (int np = 0; np < 16; np += 2) {
                    int npp = np + (vmi >> 1);
                    uint32_t tmp[4];
                    ldsm_x4_trans(tmp, vb + (uint32_t)((npp >> 3) * 8192)
                                          + swz((uint32_t)(vkey * 128 + (npp & 7) * 16)));
                    mma_f16(o[np],     pf[kc], tmp);
                    mma_f16(o[np + 1], pf[kc], tmp + 2);
                }
            }
        }

        // ---- epilogue
        float il0 = 1.f / lacc[0], il1 = 1.f / lacc[2];
        __half* Ob = Oh + ((size_t)(b * Tn + qb * FM + wid * 16)) * DMODEL + h * HD;
#pragma unroll
        for (int nt = 0; nt < 16; nt++) {
            int col = nt * 8 + cq2;
            uint32_t w0 = packh2(o[nt][0] * il0, o[nt][1] * il0);
            uint32_t w1 = packh2(o[nt][2] * il1, o[nt][3] * il1);
            *(uint32_t*)(Ob + (size_t)g * DMODEL + col)       = w0;
            *(uint32_t*)(Ob + (size_t)(g + 8) * DMODEL + col) = w1;
        }
    }
}

// ---------------- launch ----------------
extern "C" void kernel_launch(void* const* d_in, const int* in_sizes, int n_in,
                              void* d_out, int out_size) {
    (void)in_sizes; (void)n_in; (void)out_size;
    const float* x  = (const float*)d_in[0];
    const float* wq = (const float*)d_in[1];
    const float* wk = (const float*)d_in[2];
    const float* wv = (const float*)d_in[3];
    const float* wo = (const float*)d_in[4];
    float* out = (float*)d_out;

    __half *xh, *QKVh, *Vh, *Oh, *wTh, *woTh;
    cudaGetSymbolAddress((void**)&xh,   g_xh);
    cudaGetSymbolAddress((void**)&QKVh, g_QKVh);
    cudaGetSymbolAddress((void**)&Vh,   g_Vh);
    cudaGetSymbolAddress((void**)&Oh,   g_Oh);
    cudaGetSymbolAddress((void**)&wTh,  g_wTh);
    cudaGetSymbolAddress((void**)&woTh, g_woTh);

    cudaFuncSetAttribute(flash_mma,   cudaFuncAttributeMaxDynamicSharedMemorySize, FLASH_SMEM);
    cudaFuncSetAttribute(gemm_mma<0>, cudaFuncAttributeMaxDynamicSharedMemorySize, GEMM_SMEM);
    cudaFuncSetAttribute(gemm_mma<1>, cudaFuncAttributeMaxDynamicSharedMemorySize, GEMM_SMEM);

    // prep: weight transposes (fp16 K-major) + x fp16 + invf
    prep_kernel<<<PREP_BLOCKS, 256>>>(x, wq, wk, wv, wo, xh, wTh, woTh);

    // Fused QKV projection; epilogue writes fp16 QKVh + scattered fp16 Vh
    gemm_mma<1><<<dim3(QKVSTR / BN, ROWS / BM), 256, GEMM_SMEM>>>(xh, wTh, QKVh, QKVSTR);

    // RoPE in place on fp16 Q,K
    rope_kernel<<<ROPE_BLOCKS, 256>>>(QKVh);

    // Causal attention (persistent, balanced)
    flash_mma<<<NPERS, FTHREADS, FLASH_SMEM>>>(QKVh, Vh, Oh);

    // Output projection (fp32 out)
    gemm_mma<0><<<dim3(DMODEL / BN, ROWS / BM), 256, GEMM_SMEM>>>(Oh, woTh, out, DMODEL);
}

// round 16
// speedup vs baseline: 1.0893x; 1.0050x over previous
#include <cuda_runtime.h>
#include <cuda_fp16.h>
#include <math.h>
#include <stdint.h>

// ---------------- problem constants ----------------
#define Bn 2
#define Tn 2048
#define NH 16
#define NKV 4
#define HD 128
#define DMODEL 2048
#define KVDIM 512
#define QKVSTR 3072         // combined QKV row: Q[0:2048) K[2048:2560) V[2560:3072)
#define ROWS 4096           // Bn*Tn
#define GK 2048             // K dim of every GEMM

// ---------------- scratch (__device__ globals) ----------------
__device__ __half g_xh  [(size_t)ROWS * DMODEL];  // fp16 x
__device__ __half g_QKVh[(size_t)ROWS * QKVSTR];  // fp16 Q,K (roped in place); V region unused
__device__ __half g_Vh  [(size_t)ROWS * KVDIM];   // V fp16: [b][kvh][t][d]
__device__ __half g_Oh  [(size_t)ROWS * DMODEL];  // flash output fp16
__device__ __half g_wh  [(size_t)GK * QKVSTR];    // fused [wq|wk|wv] fp16, natural [K][N]
__device__ __half g_woh [(size_t)GK * DMODEL];    // wo fp16, natural [K][N]
__device__ float2 g_rt  [Tn * 64];                // rope table: (cos, sin)

// ---------------- PTX helpers (baseline sm_80+ only) ----------------
__device__ __forceinline__ uint32_t smem_u32(const void* p) {
    uint32_t a;
    asm("{ .reg .u64 t; cvta.to.shared.u64 t, %1; cvt.u32.u64 %0, t; }" : "=r"(a) : "l"(p));
    return a;
}
__device__ __forceinline__ uint32_t packh2(float lo, float hi) {   // {lo,hi} fp16x2
    uint32_t r; asm("cvt.rn.f16x2.f32 %0, %1, %2;" : "=r"(r) : "f"(hi), "f"(lo)); return r;
}
__device__ __forceinline__ uint32_t ex2h2(uint32_t x) {            // 2^x on both halves
    uint32_t r; asm("ex2.approx.f16x2 %0, %1;" : "=r"(r) : "r"(x)); return r;
}
__device__ __forceinline__ uint32_t swz(uint32_t off) {   // SW128: bits[6:4] ^= bits[9:7]
    return off ^ ((off >> 3) & 0x70);
}
__device__ __forceinline__ void cp16(uint32_t dst, const void* src) {
    asm volatile("cp.async.cg.shared.global [%0], [%1], 16;" :: "r"(dst), "l"(src) : "memory");
}
#define CP_COMMIT() asm volatile("cp.async.commit_group;" ::: "memory")
#define CP_WAIT(n)  asm volatile("cp.async.wait_group %0;" :: "n"(n) : "memory")

__device__ __forceinline__ void ldsm_x4(uint32_t* r, uint32_t addr) {
    asm volatile("ldmatrix.sync.aligned.m8n8.x4.shared.b16 {%0,%1,%2,%3}, [%4];"
                 : "=r"(r[0]), "=r"(r[1]), "=r"(r[2]), "=r"(r[3]) : "r"(addr));
}
__device__ __forceinline__ void ldsm_x4_trans(uint32_t* r, uint32_t addr) {
    asm volatile("ldmatrix.sync.aligned.m8n8.x4.trans.shared.b16 {%0,%1,%2,%3}, [%4];"
                 : "=r"(r[0]), "=r"(r[1]), "=r"(r[2]), "=r"(r[3]) : "r"(addr));
}
__device__ __forceinline__ void mma_f16(float* d, const uint32_t* a, const uint32_t* b) {
    asm volatile(
        "mma.sync.aligned.m16n8k16.row.col.f32.f16.f16.f32 "
        "{%0,%1,%2,%3}, {%4,%5,%6,%7}, {%8,%9}, {%0,%1,%2,%3};"
        : "+f"(d[0]), "+f"(d[1]), "+f"(d[2]), "+f"(d[3])
        : "r"(a[0]), "r"(a[1]), "r"(a[2]), "r"(a[3]), "r"(b[0]), "r"(b[1]));
}

// ---------------- fused prep: pure streaming converts + rope table --------
// blocks [0,4096):       wq -> g_wh cols [0,2048)
// blocks [4096,5120):    wk -> g_wh cols [2048,2560)
// blocks [5120,6144):    wv -> g_wh cols [2560,3072)
// blocks [6144,10240):   wo -> g_woh
// blocks [10240,18432):  x  -> g_xh
// blocks [18432,18944):  rope table (cos,sin)
#define PREP_BLOCKS 18944

__global__ void prep_kernel(const float* __restrict__ x,
                            const float* __restrict__ wq, const float* __restrict__ wk,
                            const float* __restrict__ wv, const float* __restrict__ wo,
                            __half* __restrict__ xh) {
    int blk = blockIdx.x;
    int tid = threadIdx.x;
    if (blk < 10240) {
        const float* src; __half* dstbase; int nchunks_row, dststride, col0, c;
        if (blk < 4096)      { src = wq; dstbase = g_wh;  nchunks_row = 512; dststride = QKVSTR; col0 = 0;    c = blk * 256 + tid; }
        else if (blk < 5120) { src = wk; dstbase = g_wh;  nchunks_row = 128; dststride = QKVSTR; col0 = 2048; c = (blk - 4096) * 256 + tid; }
        else if (blk < 6144) { src = wv; dstbase = g_wh;  nchunks_row = 128; dststride = QKVSTR; col0 = 2560; c = (blk - 5120) * 256 + tid; }
        else                 { src = wo; dstbase = g_woh; nchunks_row = 512; dststride = DMODEL; col0 = 0;    c = (blk - 6144) * 256 + tid; }
        int k = c / nchunks_row;
        int n = (c % nchunks_row) * 4;
        float4 v = ((const float4*)src)[c];
        uint2 u;
        u.x = packh2(v.x, v.y);
        u.y = packh2(v.z, v.w);
        *(uint2*)(dstbase + (size_t)k * dststride + col0 + n) = u;
    } else if (blk < 18432) {
        int i = (blk - 10240) * 256 + tid;
        float4 v = ((const float4*)x)[i];
        uint2 u;
        u.x = packh2(v.x, v.y);
        u.y = packh2(v.z, v.w);
        ((uint2*)xh)[i] = u;
    } else {
        int e = (blk - 18432) * 256 + tid;   // e < 131072
        int tt = e >> 6, d = e & 63;
        float invf = (float)exp(-((double)d / 64.0) * log(10000.0));
        float ang = (float)tt * invf;
        float sn, cs;
        sincosf(ang, &sn, &cs);
        g_rt[e] = make_float2(cs, sn);
    }
}

// ---------------- rope (in-place on fp16 QKVh; table lookup) --------------
#define ROPE_TOTQ (ROWS * NH * 64)
#define ROPE_BLOCKS 20480

__global__ void rope_kernel(__half* __restrict__ QKVh) {
    int idx = blockIdx.x * 256 + threadIdx.x;
    int off; int nheads;
    if (idx < ROPE_TOTQ) { off = 0; nheads = NH; }
    else { idx -= ROPE_TOTQ; off = 2048; nheads = NKV; }
    int d    = idx & 63;
    int rest = idx >> 6;
    int hh   = rest % nheads;
    int row  = rest / nheads;
    int tt   = row & (Tn - 1);
    float2 csn = g_rt[(tt << 6) + d];
    __half* p = QKVh + (size_t)row * QKVSTR + off + hh * HD + d;
    float x0 = __half2float(p[0]), x1 = __half2float(p[64]);
    p[0]  = __float2half_rn(x0 * csn.x - x1 * csn.y);
    p[64] = __float2half_rn(x1 * csn.x + x0 * csn.y);
}

// ---------------- fp16 mma.sync GEMM: B from natural [K][N] (trans-ldsm) --
// C[M,N] = A[M,2048] @ W[2048,N], fp16 in; W read directly (no pre-transpose).
// Block 128x128, BK=64, 3-stage cp.async, 8 warps (2x4), warp 64x32, occ 2.
// B smem tile: [nchunk(2) stride 8192][krow(64)][128B] (same layout as flash V).
#define BM 128
#define BN 128
#define NSTG 3
#define ASTG 16384
#define BSTG 16384
#define STG  (ASTG + BSTG)
#define GEMM_SMEM (NSTG * STG)   // 98304
#define KITERS 32

template <int MODE>
__global__ __launch_bounds__(256, 2)
void gemm_mma(const __half* __restrict__ A, const __half* __restrict__ W,
              void* __restrict__ Cout, int N) {
    extern __shared__ char dsm[];
    const uint32_t base = smem_u32(dsm);

    const int tid  = threadIdx.x;
    const int wid  = tid >> 5;
    const int lane = tid & 31;
    const int mb   = blockIdx.y * BM;
    const int nb   = blockIdx.x * BN;
    const int wm   = (wid & 1) * 64;
    const int wn   = (wid >> 1) * 32;

    const __half* Ag = A + (size_t)mb * GK;
    const __half* Wg = W + nb;               // [K][N] natural layout

    float acc[4][4][4];
#pragma unroll
    for (int mt = 0; mt < 4; mt++)
#pragma unroll
        for (int nt = 0; nt < 4; nt++)
#pragma unroll
            for (int q = 0; q < 4; q++) acc[mt][nt][q] = 0.f;

    auto issue = [&](int buf, int s) {
        uint32_t sa = base + (uint32_t)buf * STG;
        uint32_t sb = sa + ASTG;
        int k0 = s * 64;
#pragma unroll
        for (int i = 0; i < 4; i++) {          // A: 1024 chunks (rows of 64 halves)
            int cc  = tid + i * 256;
            int row = cc >> 3, ch = cc & 7;
            cp16(sa + swz((uint32_t)(row * 128 + ch * 16)),
                 Ag + (size_t)row * GK + k0 + ch * 8);
        }
#pragma unroll
        for (int i = 0; i < 4; i++) {          // B: 1024 chunks ([64 k][128 n])
            int cc  = tid + i * 256;
            int kr = cc >> 4, ch = cc & 15;
            cp16(sb + (uint32_t)((ch >> 3) * 8192) + swz((uint32_t)(kr * 128 + (ch & 7) * 16)),
                 Wg + (size_t)(k0 + kr) * N + ch * 8);
        }
        CP_COMMIT();
    };

    issue(0, 0); issue(1, 1);

    const int a_r  = (lane & 7) + ((lane >> 3) & 1) * 8;
    const int a_kc = (lane >> 4);
    const int vrow = lane & 7;
    const int vmi  = lane >> 3;

    int st = 0, stp = 2;
    for (int s = 0; s < KITERS; s++) {
        if (s + 2 < KITERS) CP_WAIT(1); else CP_WAIT(0);
        __syncthreads();
        if (s + 2 < KITERS) issue(stp, s + 2);

        uint32_t sa = base + (uint32_t)st * STG + (uint32_t)(wm * 128);
        uint32_t sb = base + (uint32_t)st * STG + ASTG;

#pragma unroll
        for (int ks = 0; ks < 4; ks++) {       // k16 chunks within BK=64
            uint32_t afr[4][4];
            uint32_t bfr[4][2];
#pragma unroll
            for (int mt = 0; mt < 4; mt++)
                ldsm_x4(afr[mt], sa + swz((uint32_t)((mt * 16 + a_r) * 128 + (2 * ks + a_kc) * 16)));
            {
                int vkey = ks * 16 + (vmi & 1) * 8 + vrow;
#pragma unroll
                for (int j = 0; j < 2; j++) {
                    int npp = (wn >> 3) + 2 * j + (vmi >> 1);
                    uint32_t tmp[4];
                    ldsm_x4_trans(tmp, sb + (uint32_t)((npp >> 3) * 8192)
                                         + swz((uint32_t)(vkey * 128 + (npp & 7) * 16)));
                    bfr[2 * j][0] = tmp[0]; bfr[2 * j][1] = tmp[1];
                    bfr[2 * j + 1][0] = tmp[2]; bfr[2 * j + 1][1] = tmp[3];
                }
            }
#pragma unroll
            for (int mt = 0; mt < 4; mt++)
#pragma unroll
                for (int nt = 0; nt < 4; nt++)
                    mma_f16(acc[mt][nt], afr[mt], bfr[nt]);
        }
        st  = (st  == NSTG - 1) ? 0 : st + 1;
        stp = (stp == NSTG - 1) ? 0 : stp + 1;
    }

    const int g = lane >> 2;
    const int cq = (lane & 3) * 2;
#pragma unroll
    for (int mt = 0; mt < 4; mt++) {
        int row0 = mb + wm + mt * 16 + g;
#pragma unroll
        for (int nt = 0; nt < 4; nt++) {
            int col = nb + wn + nt * 8 + cq;
            if (MODE == 0) {
                float* C = (float*)Cout;
                *(float2*)(C + (size_t)row0 * N + col)       = make_float2(acc[mt][nt][0], acc[mt][nt][1]);
                *(float2*)(C + (size_t)(row0 + 8) * N + col) = make_float2(acc[mt][nt][2], acc[mt][nt][3]);
            } else {
                uint32_t w0 = packh2(acc[mt][nt][0], acc[mt][nt][1]);
                uint32_t w1 = packh2(acc[mt][nt][2], acc[mt][nt][3]);
                if (col < 2560) {
                    __half* C = (__half*)Cout;
                    *(uint32_t*)(C + (size_t)row0 * QKVSTR + col)       = w0;
                    *(uint32_t*)(C + (size_t)(row0 + 8) * QKVSTR + col) = w1;
                } else {
                    int rel = col - 2560;
                    int kvh = rel >> 7, d = rel & 127;
                    int b0 = row0 >> 11, t0 = row0 & (Tn - 1);
                    int b1 = (row0 + 8) >> 11, t1 = (row0 + 8) & (Tn - 1);
                    *(uint32_t*)(g_Vh + (((size_t)(b0 * NKV + kvh) * Tn + t0) * HD + d)) = w0;
                    *(uint32_t*)(g_Vh + (((size_t)(b1 * NKV + kvh) * Tn + t1) * HD + d)) = w1;
                }
            }
        }
    }
}

// ---------------- flash attention (R15 persistent config, unchanged) ------
#define FM 64
#define FN 64
#define KVBUF 32768
#define FLASH_SMEM (16384 + 2 * KVBUF)   // 81920
#define FTHREADS 128
#define NJOBS 1024
#define NPERS 296

__global__ __launch_bounds__(FTHREADS, 2)
void flash_mma(const __half* __restrict__ QKVh, const __half* __restrict__ Vh,
               __half* __restrict__ Oh) {
    extern __shared__ float sm[];
    const uint32_t base = smem_u32(sm);
    const int tid = threadIdx.x, wid = tid >> 5, lane = tid & 31;

    const int a_r  = (lane & 7) + ((lane >> 3) & 1) * 8;
    const int a_kc = lane >> 4;
    const int b_r  = (lane & 7) + (lane >> 4) * 8;
    const int b_kc = (lane >> 3) & 1;
    const int g    = lane >> 2;
    const int cq2  = (lane & 3) * 2;
    const int vrow = lane & 7;
    const int vmi  = lane >> 3;
    const float scale2 = 0.08838834764831843f * 1.4426950408889634f;
    const uint32_t ONESx2 = 0x3C003C00u;
    const uint32_t bones[2] = {ONESx2, ONESx2};

    for (int job = blockIdx.x; job < NJOBS; job += NPERS) {
        const int qb = 31 - (job >> 5);
        const int hb = job & 31;
        const int h = hb & 15, b = hb >> 4;
        const int kvh = h >> 2;
        const int nkt = qb + 1;

        const __half* Qg = QKVh + ((size_t)(b * Tn + qb * FM)) * QKVSTR + h * HD;
        const __half* Kg = QKVh + ((size_t)(b * Tn)) * QKVSTR + 2048 + kvh * HD;
        const __half* Vg = Vh + ((size_t)(b * NKV + kvh)) * Tn * HD;

        __syncthreads();

#pragma unroll
        for (int i = 0; i < 8; i++) {
            int f = tid + i * FTHREADS;
            int qr = f >> 4, ch = f & 15;
            cp16(base + (uint32_t)((ch >> 3) * 8192) + swz((uint32_t)(qr * 128 + (ch & 7) * 16)),
                 Qg + (size_t)qr * QKVSTR + ch * 8);
        }

        auto kv_issue = [&](int kt) {
            uint32_t kb = base + 16384u + (uint32_t)(kt & 1) * KVBUF;
            uint32_t vb = kb + 16384u;
            const __half* Ksrc = Kg + (size_t)(kt * FN) * QKVSTR;
            const __half* Vsrc = Vg + (size_t)(kt * FN) * HD;
#pragma unroll
            for (int i = 0; i < 8; i++) {
                int f = tid + i * FTHREADS;
                int kr = f >> 4, ch = f & 15;
                cp16(kb + (uint32_t)((ch >> 3) * 8192) + swz((uint32_t)(kr * 128 + (ch & 7) * 16)),
                     Ksrc + (size_t)kr * QKVSTR + ch * 8);
            }
#pragma unroll
            for (int i = 0; i < 8; i++) {
                int f = tid + i * FTHREADS;
                int key = f >> 4, ch = f & 15;
                cp16(vb + (uint32_t)((ch >> 3) * 8192) + swz((uint32_t)(key * 128 + (ch & 7) * 16)),
                     Vsrc + key * HD + ch * 8);
            }
            CP_COMMIT();
        };

        float o[16][4];
#pragma unroll
        for (int nt = 0; nt < 16; nt++)
#pragma unroll
            for (int q = 0; q < 4; q++) o[nt][q] = 0.f;
        float lacc[4] = {0.f, 0.f, 0.f, 0.f};
        float m0 = -1e30f, m1 = -1e30f;

        kv_issue(0);

        for (int kt = 0; kt < nkt; kt++) {
            __syncthreads();
            if (kt + 1 < nkt) { kv_issue(kt + 1); CP_WAIT(1); }
            else              { CP_WAIT(0); }
            __syncthreads();

            uint32_t kb = base + 16384u + (uint32_t)(kt & 1) * KVBUF;
            uint32_t vb = kb + 16384u;

            float sacc[8][4];
#pragma unroll
            for (int nt = 0; nt < 8; nt++)
#pragma unroll
                for (int q = 0; q < 4; q++) sacc[nt][q] = 0.f;

#pragma unroll
            for (int ks = 0; ks < 8; ks++) {
                uint32_t af[4];
                ldsm_x4(af, base + (uint32_t)((ks >> 2) * 8192)
                            + swz((uint32_t)((wid * 16 + a_r) * 128 + ((ks & 3) * 2 + a_kc) * 16)));
                uint32_t bf[8][2];
#pragma unroll
                for (int np = 0; np < 4; np++) {
                    uint32_t tmp[4];
                    ldsm_x4(tmp, kb + (uint32_t)((ks >> 2) * 8192)
                                 + swz((uint32_t)((np * 16 + b_r) * 128 + ((ks & 3) * 2 + b_kc) * 16)));
                    bf[np * 2][0] = tmp[0]; bf[np * 2][1] = tmp[1];
                    bf[np * 2 + 1][0] = tmp[2]; bf[np * 2 + 1][1] = tmp[3];
                }
#pragma unroll
                for (int nt = 0; nt < 8; nt++) mma_f16(sacc[nt], af, bf[nt]);
            }

            if (kt == qb) {
                int rl0 = wid * 16 + g, rl1 = rl0 + 8;
#pragma unroll
                for (int nt = 0; nt < 8; nt++) {
                    int kc0 = nt * 8 + cq2;
                    sacc[nt][0] = (kc0     > rl0) ? -1e30f : sacc[nt][0] * scale2;
                    sacc[nt][1] = (kc0 + 1 > rl0) ? -1e30f : sacc[nt][1] * scale2;
                    sacc[nt][2] = (kc0     > rl1) ? -1e30f : sacc[nt][2] * scale2;
                    sacc[nt][3] = (kc0 + 1 > rl1) ? -1e30f : sacc[nt][3] * scale2;
                }
            } else {
#pragma unroll
                for (int nt = 0; nt < 8; nt++)
#pragma unroll
                    for (int q = 0; q < 4; q++) sacc[nt][q] *= scale2;
            }

            float mx0 = -1e30f, mx1 = -1e30f;
#pragma unroll
            for (int nt = 0; nt < 8; nt++) {
                mx0 = fmaxf(mx0, fmaxf(sacc[nt][0], sacc[nt][1]));
                mx1 = fmaxf(mx1, fmaxf(sacc[nt][2], sacc[nt][3]));
            }
            mx0 = fmaxf(mx0, __shfl_xor_sync(0xffffffffu, mx0, 1));
            mx0 = fmaxf(mx0, __shfl_xor_sync(0xffffffffu, mx0, 2));
            mx1 = fmaxf(mx1, __shfl_xor_sync(0xffffffffu, mx1, 1));
            mx1 = fmaxf(mx1, __shfl_xor_sync(0xffffffffu, mx1, 2));
            float nm0 = fmaxf(m0, mx0), nm1 = fmaxf(m1, mx1);
            float al0 = exp2f(m0 - nm0), al1 = exp2f(m1 - nm1);
            m0 = nm0; m1 = nm1;

            uint32_t pf[4][4];
#pragma unroll
            for (int kc = 0; kc < 4; kc++) {
                pf[kc][0] = ex2h2(packh2(sacc[2 * kc][0] - nm0,     sacc[2 * kc][1] - nm0));
                pf[kc][1] = ex2h2(packh2(sacc[2 * kc][2] - nm1,     sacc[2 * kc][3] - nm1));
                pf[kc][2] = ex2h2(packh2(sacc[2 * kc + 1][0] - nm0, sacc[2 * kc + 1][1] - nm0));
                pf[kc][3] = ex2h2(packh2(sacc[2 * kc + 1][2] - nm1, sacc[2 * kc + 1][3] - nm1));
            }

#pragma unroll
            for (int nt = 0; nt < 16; nt++) {
                o[nt][0] *= al0; o[nt][1] *= al0;
                o[nt][2] *= al1; o[nt][3] *= al1;
            }
            lacc[0] *= al0; lacc[1] *= al0;
            lacc[2] *= al1; lacc[3] *= al1;

#pragma unroll
            for (int kc = 0; kc < 4; kc++) mma_f16(lacc, pf[kc], bones);

#pragma unroll
            for (int kc = 0; kc < 4; kc++) {
                int vkey = kc * 16 + (vmi & 1) * 8 + vrow;
#pragma unroll
                for (int np = 0; np < 16; np += 2) {
                    int npp = np + (vmi >> 1);
                    uint32_t tmp[4];
                    ldsm_x4_trans(tmp, vb + (uint32_t)((npp >> 3) * 8192)
                                          + swz((uint32_t)(vkey * 128 + (npp & 7) * 16)));
                    mma_f16(o[np],     pf[kc], tmp);
                    mma_f16(o[np + 1], pf[kc], tmp + 2);
                }
            }
        }

        float il0 = 1.f / lacc[0], il1 = 1.f / lacc[2];
        __half* Ob = Oh + ((size_t)(b * Tn + qb * FM + wid * 16)) * DMODEL + h * HD;
#pragma unroll
        for (int nt = 0; nt < 16; nt++) {
            int col = nt * 8 + cq2;
            uint32_t w0 = packh2(o[nt][0] * il0, o[nt][1] * il0);
            uint32_t w1 = packh2(o[nt][2] * il1, o[nt][3] * il1);
            *(uint32_t*)(Ob + (size_t)g * DMODEL + col)       = w0;
            *(uint32_t*)(Ob + (size_t)(g + 8) * DMODEL + col) = w1;
        }
    }
}

// ---------------- launch ----------------
extern "C" void kernel_launch(void* const* d_in, const int* in_sizes, int n_in,
                              void* d_out, int out_size) {
    (void)in_sizes; (void)n_in; (void)out_size;
    const float* x  = (const float*)d_in[0];
    const float* wq = (const float*)d_in[1];
    const float* wk = (const float*)d_in[2];
    const float* wv = (const float*)d_in[3];
    const float* wo = (const float*)d_in[4];
    float* out = (float*)d_out;

    __half *xh, *QKVh, *Vh, *Oh, *wh, *woh;
    cudaGetSymbolAddress((void**)&xh,   g_xh);
    cudaGetSymbolAddress((void**)&QKVh, g_QKVh);
    cudaGetSymbolAddress((void**)&Vh,   g_Vh);
    cudaGetSymbolAddress((void**)&Oh,   g_Oh);
    cudaGetSymbolAddress((void**)&wh,   g_wh);
    cudaGetSymbolAddress((void**)&woh,  g_woh);

    cudaFuncSetAttribute(flash_mma,   cudaFuncAttributeMaxDynamicSharedMemorySize, FLASH_SMEM);
    cudaFuncSetAttribute(gemm_mma<0>, cudaFuncAttributeMaxDynamicSharedMemorySize, GEMM_SMEM);
    cudaFuncSetAttribute(gemm_mma<1>, cudaFuncAttributeMaxDynamicSharedMemorySize, GEMM_SMEM);

    // prep: streaming fp16 converts (no transposes) + rope table
    prep_kernel<<<PREP_BLOCKS, 256>>>(x, wq, wk, wv, wo, xh);

    // Fused QKV projection; W consumed in natural [K][N] layout
    gemm_mma<1><<<dim3(QKVSTR / BN, ROWS / BM), 256, GEMM_SMEM>>>(xh, wh, QKVh, QKVSTR);

    // RoPE in place on fp16 Q,K (table lookup)
    rope_kernel<<<ROPE_BLOCKS, 256>>>(QKVh);

    // Causal attention (persistent)
    flash_mma<<<NPERS, FTHREADS, FLASH_SMEM>>>(QKVh, Vh, Oh);

    // Output projection (fp32 out)
    gemm_mma<0><<<dim3(DMODEL / BN, ROWS / BM), 256, GEMM_SMEM>>>(Oh, woh, out, DMODEL);
}